// round 9
// baseline (speedup 1.0000x reference)
#include <cuda_runtime.h>

// Locally connected 2D:
//   y[n,h,w] = relu( sum_{i,j} x[n,h+i,w+j] * W[h,w,i,j] + b[h,w] )
// N=64, H_IN=W_IN=512, K=9, H_OUT=W_OUT=504.
//
// CTA: 256 threads = 8 warps = 4 h-rows x 2 w-halves. Each lane owns TWO
// batches (n = lane, lane+32) with independent scalar accumulators, so each
// warp-uniform weight broadcast LDS feeds 108 FFMAs instead of 54 -> smem
// crossbar cycles per output drop 25% (crossbar is the measured binder:
// L1=73%, fma=18%). Tile: 4h x 12w x 64n (504 = 42*12 = 126*4).
// x staged [r][n][c] pitch 20 (sliding window = 3xLDS.128 + LDS.64);
// weights packed [hl][i][wh][half][28] -> 7x broadcast LDS.128 per half.

#define TW 12            // w outputs per CTA
#define WH 6             // w outputs per thread
#define TH 4             // h rows per CTA
#define XR (TH + 8)      // 12 x rows staged
#define CP 20            // x cols staged per n (col pitch, floats)
#define RSTRIDE (64 * CP + 4)   // 1284 floats
#define PIX (TH * TW)    // 48 pixels per CTA

// smem (floats): XS[XR][RSTRIDE] = 15408 ; WS[4][9][2][2][28] = 4032
#define XS_OFF 0
#define WS_OFF (XR * RSTRIDE)                      // 15408
#define SMEM_FLOATS (WS_OFF + 4 * 9 * 2 * 2 * 28)  // 19440
#define SMEM_BYTES (SMEM_FLOATS * 4)               // 77760

template<int WHI>   // w-half index: 0 or 1
__device__ __forceinline__
void load_window(const float* __restrict__ xrow, float* __restrict__ xw)
{
    if (WHI == 0) {
        float4 a = *reinterpret_cast<const float4*>(xrow + 0);
        float4 b = *reinterpret_cast<const float4*>(xrow + 4);
        float4 c = *reinterpret_cast<const float4*>(xrow + 8);
        float2 d = *reinterpret_cast<const float2*>(xrow + 12);
        xw[0]=a.x; xw[1]=a.y; xw[2]=a.z; xw[3]=a.w;
        xw[4]=b.x; xw[5]=b.y; xw[6]=b.z; xw[7]=b.w;
        xw[8]=c.x; xw[9]=c.y; xw[10]=c.z; xw[11]=c.w;
        xw[12]=d.x; xw[13]=d.y;
    } else {
        // window starts at col 6 (not 16B-aligned): f2 then 3x f4
        float2 d = *reinterpret_cast<const float2*>(xrow + 0);
        float4 a = *reinterpret_cast<const float4*>(xrow + 2);
        float4 b = *reinterpret_cast<const float4*>(xrow + 6);
        float4 c = *reinterpret_cast<const float4*>(xrow + 10);
        xw[0]=d.x; xw[1]=d.y;
        xw[2]=a.x; xw[3]=a.y; xw[4]=a.z; xw[5]=a.w;
        xw[6]=b.x; xw[7]=b.y; xw[8]=b.z; xw[9]=b.w;
        xw[10]=c.x; xw[11]=c.y; xw[12]=c.z; xw[13]=c.w;
    }
}

template<int WHI>
__device__ __forceinline__
void lc2d_compute(const float* __restrict__ XS, const float* __restrict__ WS,
                  const float* __restrict__ bp,
                  float* __restrict__ dstA, float* __restrict__ dstB,
                  int hl, int lane)
{
    float accA[WH], accB[WH];
#pragma unroll
    for (int o = 0; o < WH; o++) { accA[o] = 0.0f; accB[o] = 0.0f; }

#pragma unroll
    for (int i = 0; i < 9; i++) {
        const int r = hl + i;
        const float* xbase = XS + r * RSTRIDE + (WHI ? 6 : 0);
        float xwA[14], xwB[14];
        load_window<WHI>(xbase + lane * CP,        xwA);   // batch n = lane
        load_window<WHI>(xbase + (lane + 32) * CP, xwB);   // batch n = lane+32

        const float* wrow = WS + (((hl * 9 + i) * 2 + WHI) * 2) * 28;

#pragma unroll
        for (int half = 0; half < 2; half++) {
            const float* wb = wrow + half * 28;
            float w[28];
#pragma unroll
            for (int k = 0; k < 7; k++) {
                float4 v = *reinterpret_cast<const float4*>(wb + 4 * k);  // broadcast
                w[4*k+0]=v.x; w[4*k+1]=v.y; w[4*k+2]=v.z; w[4*k+3]=v.w;
            }
#pragma unroll
            for (int ol = 0; ol < 3; ol++) {
                const int o = half * 3 + ol;
                float a = accA[o];
                float b = accB[o];
#pragma unroll
                for (int j = 0; j < 9; j++) {
                    const float wv = w[ol * 9 + j];
                    a = fmaf(xwA[o + j], wv, a);
                    b = fmaf(xwB[o + j], wv, b);
                }
                accA[o] = a;
                accB[o] = b;
            }
        }
    }

    // bias + relu + direct stores (3x STG.64 per batch)
    float bias6[WH];
#pragma unroll
    for (int o = 0; o < WH; o++) bias6[o] = __ldg(bp + o);

    float a0 = fmaxf(accA[0] + bias6[0], 0.0f);
    float a1 = fmaxf(accA[1] + bias6[1], 0.0f);
    float a2 = fmaxf(accA[2] + bias6[2], 0.0f);
    float a3 = fmaxf(accA[3] + bias6[3], 0.0f);
    float a4 = fmaxf(accA[4] + bias6[4], 0.0f);
    float a5 = fmaxf(accA[5] + bias6[5], 0.0f);
    reinterpret_cast<float2*>(dstA)[0] = make_float2(a0, a1);
    reinterpret_cast<float2*>(dstA)[1] = make_float2(a2, a3);
    reinterpret_cast<float2*>(dstA)[2] = make_float2(a4, a5);

    float b0 = fmaxf(accB[0] + bias6[0], 0.0f);
    float b1 = fmaxf(accB[1] + bias6[1], 0.0f);
    float b2 = fmaxf(accB[2] + bias6[2], 0.0f);
    float b3 = fmaxf(accB[3] + bias6[3], 0.0f);
    float b4 = fmaxf(accB[4] + bias6[4], 0.0f);
    float b5 = fmaxf(accB[5] + bias6[5], 0.0f);
    reinterpret_cast<float2*>(dstB)[0] = make_float2(b0, b1);
    reinterpret_cast<float2*>(dstB)[1] = make_float2(b2, b3);
    reinterpret_cast<float2*>(dstB)[2] = make_float2(b4, b5);
}

__global__ __launch_bounds__(256, 2)
void lc2d_kernel(const float* __restrict__ x,
                 const float* __restrict__ wgt,
                 const float* __restrict__ bias,
                 float* __restrict__ out)
{
    extern __shared__ float sm[];
    float* XS = sm + XS_OFF;
    float* WS = sm + WS_OFF;

    const int tid  = threadIdx.x;
    const int lane = tid & 31;
    const int warp = tid >> 5;

    const int w0 = blockIdx.x * TW;   // 0..492
    const int h0 = blockIdx.y * TH;   // 0..500

    // ---- stage x: x[n, h0+r, w0+4c4..+3] -> XS[r*RSTRIDE + n*CP + 4c4] ----
    // 64 n * 60 f4/n over 256 threads: 4 threads per n, 15 f4 each (exact).
    {
        const int nn = tid >> 2;       // 0..63
        const int s  = tid & 3;
        const float* src = x + (size_t)nn * (512 * 512) + (size_t)h0 * 512 + w0;
        float* dstn = XS + nn * CP;
#pragma unroll
        for (int k = 0; k < 15; k++) {
            int m  = s + 4 * k;        // 0..59, exact cover
            int r  = m / 5;
            int c4 = m - r * 5;
            float4 v = *reinterpret_cast<const float4*>(src + r * 512 + c4 * 4);
            *reinterpret_cast<float4*>(dstn + r * RSTRIDE + c4 * 4) = v;
        }
    }

    // ---- stage weights: W[h0+hl, w0+o, i, j] -> WS[hl][i][wh][half][wi*9+j]
    {
        for (int t = tid; t < PIX * 81; t += 256) {   // 48*81 = 3888
            int pix = t / 81;          // hl*12 + o
            int q   = t - pix * 81;
            int i   = q / 9;
            int j   = q - i * 9;
            int hl  = pix / TW;
            int o   = pix - hl * TW;   // 0..11
            int wh  = o / 6;
            int ol  = o - wh * 6;      // 0..5
            int hf  = ol / 3;
            int wi  = ol - hf * 3;     // 0..2
            WS[(((hl * 9 + i) * 2 + wh) * 2 + hf) * 28 + wi * 9 + j] =
                wgt[((size_t)(h0 + hl) * 504 + (w0 + o)) * 81 + q];
        }
    }

    __syncthreads();

    // ---- compute: warp = (hl, wh); each lane does batches lane & lane+32 ----
    const int hl = warp >> 1;          // 0..3
    const int wh = warp & 1;           // 0..1
    const int h  = h0 + hl;
    const int cbase = wh * WH;         // 0 or 6

    const float* bp   = bias + (size_t)h * 504 + w0 + cbase;
    float* dstA = out + ((size_t)lane        * 504 + h) * 504 + w0 + cbase;
    float* dstB = out + ((size_t)(lane + 32) * 504 + h) * 504 + w0 + cbase;

    if (wh == 0) lc2d_compute<0>(XS, WS, bp, dstA, dstB, hl, lane);
    else         lc2d_compute<1>(XS, WS, bp, dstA, dstB, hl, lane);
}

extern "C" void kernel_launch(void* const* d_in, const int* in_sizes, int n_in,
                              void* d_out, int out_size)
{
    const float* x    = (const float*)d_in[0];
    const float* wgt  = (const float*)d_in[1];
    const float* bias = (const float*)d_in[2];
    float* out        = (float*)d_out;

    cudaFuncSetAttribute(lc2d_kernel,
                         cudaFuncAttributeMaxDynamicSharedMemorySize,
                         SMEM_BYTES);

    dim3 grid(504 / TW, 504 / TH);   // 42 x 126 = 5292 CTAs
    lc2d_kernel<<<grid, 256, SMEM_BYTES>>>(x, wgt, bias, out);
}

// round 10
// speedup vs baseline: 1.0802x; 1.0802x over previous
#include <cuda_runtime.h>

// Locally connected 2D:
//   y[n,h,w] = relu( sum_{i,j} x[n,h+i,w+j] * W[h,w,i,j] + b[h,w] )
// N=64, H_IN=W_IN=512, K=9, H_OUT=W_OUT=504.
//
// CTA: 384 threads = 12 warps = 6 h-rows x 2 w-halves; 2 CTAs/SM = 24 warps.
// Each lane owns TWO batches (n = lane, lane+32) with independent scalar
// accumulators -> each warp-uniform weight broadcast feeds 108 FFMAs
// (crossbar diet proven in round 9: L1 73% -> 53%). Round 9's loss was warp
// count (16/SM); TH=6 restores 24/SM at 96KB smem.
// Tile: 6h x 12w x 64n (exact: 504 = 42*12 = 84*6).
// x staged [r][n][c] pitch 20 (window = 3xLDS.128 + LDS.64);
// weights packed [hl][i][wh][half][28] -> 7x broadcast LDS.128 per half.

#define TW 12            // w outputs per CTA
#define WH 6             // w outputs per thread
#define TH 6             // h rows per CTA
#define XR (TH + 8)      // 14 x rows staged
#define CP 20            // x cols staged per n (col pitch, floats)
#define RSTRIDE (64 * CP + 4)   // 1284 floats
#define PIX (TH * TW)    // 72 pixels per CTA

// smem (floats): XS[XR][RSTRIDE] = 17976 ; WS[6][9][2][2][28] = 6048
#define XS_OFF 0
#define WS_OFF (XR * RSTRIDE)                      // 17976
#define SMEM_FLOATS (WS_OFF + TH * 9 * 2 * 2 * 28) // 24024
#define SMEM_BYTES (SMEM_FLOATS * 4)               // 96096

template<int WHI>   // w-half index: 0 or 1
__device__ __forceinline__
void load_window(const float* __restrict__ xrow, float* __restrict__ xw)
{
    if (WHI == 0) {
        float4 a = *reinterpret_cast<const float4*>(xrow + 0);
        float4 b = *reinterpret_cast<const float4*>(xrow + 4);
        float4 c = *reinterpret_cast<const float4*>(xrow + 8);
        float2 d = *reinterpret_cast<const float2*>(xrow + 12);
        xw[0]=a.x; xw[1]=a.y; xw[2]=a.z; xw[3]=a.w;
        xw[4]=b.x; xw[5]=b.y; xw[6]=b.z; xw[7]=b.w;
        xw[8]=c.x; xw[9]=c.y; xw[10]=c.z; xw[11]=c.w;
        xw[12]=d.x; xw[13]=d.y;
    } else {
        // window starts at col 6 (not 16B-aligned): f2 then 3x f4
        float2 d = *reinterpret_cast<const float2*>(xrow + 0);
        float4 a = *reinterpret_cast<const float4*>(xrow + 2);
        float4 b = *reinterpret_cast<const float4*>(xrow + 6);
        float4 c = *reinterpret_cast<const float4*>(xrow + 10);
        xw[0]=d.x; xw[1]=d.y;
        xw[2]=a.x; xw[3]=a.y; xw[4]=a.z; xw[5]=a.w;
        xw[6]=b.x; xw[7]=b.y; xw[8]=b.z; xw[9]=b.w;
        xw[10]=c.x; xw[11]=c.y; xw[12]=c.z; xw[13]=c.w;
    }
}

template<int WHI>
__device__ __forceinline__
void lc2d_compute(const float* __restrict__ XS, const float* __restrict__ WS,
                  const float* __restrict__ bp,
                  float* __restrict__ dstA, float* __restrict__ dstB,
                  int hl, int lane)
{
    float accA[WH], accB[WH];
#pragma unroll
    for (int o = 0; o < WH; o++) { accA[o] = 0.0f; accB[o] = 0.0f; }

#pragma unroll
    for (int i = 0; i < 9; i++) {
        const int r = hl + i;
        const float* xbase = XS + r * RSTRIDE + (WHI ? 6 : 0);
        float xwA[14], xwB[14];
        load_window<WHI>(xbase + lane * CP,        xwA);   // batch n = lane
        load_window<WHI>(xbase + (lane + 32) * CP, xwB);   // batch n = lane+32

        const float* wrow = WS + (((hl * 9 + i) * 2 + WHI) * 2) * 28;

#pragma unroll
        for (int half = 0; half < 2; half++) {
            const float* wb = wrow + half * 28;
            float w[28];
#pragma unroll
            for (int k = 0; k < 7; k++) {
                float4 v = *reinterpret_cast<const float4*>(wb + 4 * k);  // broadcast
                w[4*k+0]=v.x; w[4*k+1]=v.y; w[4*k+2]=v.z; w[4*k+3]=v.w;
            }
#pragma unroll
            for (int ol = 0; ol < 3; ol++) {
                const int o = half * 3 + ol;
                float a = accA[o];
                float b = accB[o];
#pragma unroll
                for (int j = 0; j < 9; j++) {
                    const float wv = w[ol * 9 + j];
                    a = fmaf(xwA[o + j], wv, a);
                    b = fmaf(xwB[o + j], wv, b);
                }
                accA[o] = a;
                accB[o] = b;
            }
        }
    }

    // bias + relu + direct stores (3x STG.64 per batch)
    float bias6[WH];
#pragma unroll
    for (int o = 0; o < WH; o++) bias6[o] = __ldg(bp + o);

    float a0 = fmaxf(accA[0] + bias6[0], 0.0f);
    float a1 = fmaxf(accA[1] + bias6[1], 0.0f);
    float a2 = fmaxf(accA[2] + bias6[2], 0.0f);
    float a3 = fmaxf(accA[3] + bias6[3], 0.0f);
    float a4 = fmaxf(accA[4] + bias6[4], 0.0f);
    float a5 = fmaxf(accA[5] + bias6[5], 0.0f);
    reinterpret_cast<float2*>(dstA)[0] = make_float2(a0, a1);
    reinterpret_cast<float2*>(dstA)[1] = make_float2(a2, a3);
    reinterpret_cast<float2*>(dstA)[2] = make_float2(a4, a5);

    float b0 = fmaxf(accB[0] + bias6[0], 0.0f);
    float b1 = fmaxf(accB[1] + bias6[1], 0.0f);
    float b2 = fmaxf(accB[2] + bias6[2], 0.0f);
    float b3 = fmaxf(accB[3] + bias6[3], 0.0f);
    float b4 = fmaxf(accB[4] + bias6[4], 0.0f);
    float b5 = fmaxf(accB[5] + bias6[5], 0.0f);
    reinterpret_cast<float2*>(dstB)[0] = make_float2(b0, b1);
    reinterpret_cast<float2*>(dstB)[1] = make_float2(b2, b3);
    reinterpret_cast<float2*>(dstB)[2] = make_float2(b4, b5);
}

__global__ __launch_bounds__(384, 2)
void lc2d_kernel(const float* __restrict__ x,
                 const float* __restrict__ wgt,
                 const float* __restrict__ bias,
                 float* __restrict__ out)
{
    extern __shared__ float sm[];
    float* XS = sm + XS_OFF;
    float* WS = sm + WS_OFF;

    const int tid  = threadIdx.x;
    const int lane = tid & 31;
    const int warp = tid >> 5;

    const int w0 = blockIdx.x * TW;   // 0..492
    const int h0 = blockIdx.y * TH;   // 0..498

    // ---- stage x: x[n, h0+r, w0+4c4..+3] -> XS[r*RSTRIDE + n*CP + 4c4] ----
    // 64 n * 14 r * 5 f4 = 4480 f4 over 384 threads: 6 threads per n,
    // each covers m = s + 6k (m < 70).
    {
        const int nn = tid / 6;        // 0..63
        const int s  = tid - nn * 6;   // 0..5
        const float* src = x + (size_t)nn * (512 * 512) + (size_t)h0 * 512 + w0;
        float* dstn = XS + nn * CP;
#pragma unroll
        for (int k = 0; k < 12; k++) {
            int m = s + 6 * k;         // 0..71
            if (m < 70) {
                int r  = m / 5;
                int c4 = m - r * 5;
                float4 v = *reinterpret_cast<const float4*>(src + r * 512 + c4 * 4);
                *reinterpret_cast<float4*>(dstn + r * RSTRIDE + c4 * 4) = v;
            }
        }
    }

    // ---- stage weights: W[h0+hl, w0+o, i, j] -> WS[hl][i][wh][half][wi*9+j]
    {
        for (int t = tid; t < PIX * 81; t += 384) {   // 72*81 = 5832
            int pix = t / 81;          // hl*12 + o
            int q   = t - pix * 81;
            int i   = q / 9;
            int j   = q - i * 9;
            int hl  = pix / TW;
            int o   = pix - hl * TW;   // 0..11
            int wh  = o / 6;
            int ol  = o - wh * 6;      // 0..5
            int hf  = ol / 3;
            int wi  = ol - hf * 3;     // 0..2
            WS[(((hl * 9 + i) * 2 + wh) * 2 + hf) * 28 + wi * 9 + j] =
                wgt[((size_t)(h0 + hl) * 504 + (w0 + o)) * 81 + q];
        }
    }

    __syncthreads();

    // ---- compute: warp = (hl, wh); each lane does batches lane & lane+32 ----
    const int hl = warp >> 1;          // 0..5
    const int wh = warp & 1;           // 0..1
    const int h  = h0 + hl;
    const int cbase = wh * WH;         // 0 or 6

    const float* bp   = bias + (size_t)h * 504 + w0 + cbase;
    float* dstA = out + ((size_t)lane        * 504 + h) * 504 + w0 + cbase;
    float* dstB = out + ((size_t)(lane + 32) * 504 + h) * 504 + w0 + cbase;

    if (wh == 0) lc2d_compute<0>(XS, WS, bp, dstA, dstB, hl, lane);
    else         lc2d_compute<1>(XS, WS, bp, dstA, dstB, hl, lane);
}

extern "C" void kernel_launch(void* const* d_in, const int* in_sizes, int n_in,
                              void* d_out, int out_size)
{
    const float* x    = (const float*)d_in[0];
    const float* wgt  = (const float*)d_in[1];
    const float* bias = (const float*)d_in[2];
    float* out        = (float*)d_out;

    cudaFuncSetAttribute(lc2d_kernel,
                         cudaFuncAttributeMaxDynamicSharedMemorySize,
                         SMEM_BYTES);

    dim3 grid(504 / TW, 504 / TH);   // 42 x 84 = 3528 CTAs
    lc2d_kernel<<<grid, 384, SMEM_BYTES>>>(x, wgt, bias, out);
}

// round 11
// speedup vs baseline: 1.0880x; 1.0072x over previous
#include <cuda_runtime.h>

// Locally connected 2D:
//   y[n,h,w] = relu( sum_{i,j} x[n,h+i,w+j] * W[h,w,i,j] + b[h,w] )
// N=64, H_IN=W_IN=512, K=9, H_OUT=W_OUT=504.
//
// CTA: 256 threads = 8 warps = 4 h-pairs x 2 w-halves. Each thread computes
// TWO adjacent h rows x 6 w x TWO batches (n = lane, lane+32) = 24 outputs.
// h-register-blocking: the two h rows share 8/10 x rows, so each x window is
// loaded once and feeds both rows (x-LDS per output / 1.8). 24 independent
// FFMA chains per thread hide LDS latency via ILP (occ is smem-capped at
// 2 CTAs/SM = 16 warps). Tile: 8h x 12w x 64n (504 = 63*8 = 42*12).
// x staged [r][n][c] pitch 20 (window = 3xLDS.128 + LDS.64 per batch);
// weights packed [hloc][i][wh][half][28] -> 7x broadcast LDS.128 per half.

#define TW 12            // w outputs per CTA
#define WH 6             // w outputs per thread
#define TH 8             // h rows per CTA (4 pairs)
#define XR (TH + 8)      // 16 x rows staged
#define CP 20            // x cols staged per n (col pitch, floats)
#define RSTRIDE (64 * CP + 4)   // 1284 floats
#define PIX (TH * TW)    // 96 pixels per CTA

// smem (floats): XS[XR][RSTRIDE] = 20544 ; WS[8][9][2][2][28] = 8064
#define XS_OFF 0
#define WS_OFF (XR * RSTRIDE)                      // 20544
#define SMEM_FLOATS (WS_OFF + TH * 9 * 2 * 2 * 28) // 28608
#define SMEM_BYTES (SMEM_FLOATS * 4)               // 114432

template<int WHI>   // w-half index: 0 or 1
__device__ __forceinline__
void load_window(const float* __restrict__ xrow, float* __restrict__ xw)
{
    if (WHI == 0) {
        float4 a = *reinterpret_cast<const float4*>(xrow + 0);
        float4 b = *reinterpret_cast<const float4*>(xrow + 4);
        float4 c = *reinterpret_cast<const float4*>(xrow + 8);
        float2 d = *reinterpret_cast<const float2*>(xrow + 12);
        xw[0]=a.x; xw[1]=a.y; xw[2]=a.z; xw[3]=a.w;
        xw[4]=b.x; xw[5]=b.y; xw[6]=b.z; xw[7]=b.w;
        xw[8]=c.x; xw[9]=c.y; xw[10]=c.z; xw[11]=c.w;
        xw[12]=d.x; xw[13]=d.y;
    } else {
        // window starts at col 6 (not 16B-aligned): f2 then 3x f4
        float2 d = *reinterpret_cast<const float2*>(xrow + 0);
        float4 a = *reinterpret_cast<const float4*>(xrow + 2);
        float4 b = *reinterpret_cast<const float4*>(xrow + 6);
        float4 c = *reinterpret_cast<const float4*>(xrow + 10);
        xw[0]=d.x; xw[1]=d.y;
        xw[2]=a.x; xw[3]=a.y; xw[4]=a.z; xw[5]=a.w;
        xw[6]=b.x; xw[7]=b.y; xw[8]=b.z; xw[9]=b.w;
        xw[10]=c.x; xw[11]=c.y; xw[12]=c.z; xw[13]=c.w;
    }
}

// Accumulate one tap row for one output h-row (both batches) from the
// already-loaded windows. Weight rows: 2 halves x (7x broadcast LDS.128).
__device__ __forceinline__
void accum_row(const float* __restrict__ wrow,
               const float* __restrict__ xwA, const float* __restrict__ xwB,
               float* __restrict__ accA, float* __restrict__ accB)
{
#pragma unroll
    for (int half = 0; half < 2; half++) {
        const float* wb = wrow + half * 28;
        float w[28];
#pragma unroll
        for (int k = 0; k < 7; k++) {
            float4 v = *reinterpret_cast<const float4*>(wb + 4 * k);  // broadcast
            w[4*k+0]=v.x; w[4*k+1]=v.y; w[4*k+2]=v.z; w[4*k+3]=v.w;
        }
#pragma unroll
        for (int ol = 0; ol < 3; ol++) {
            const int o = half * 3 + ol;
            float a = accA[o];
            float b = accB[o];
#pragma unroll
            for (int j = 0; j < 9; j++) {
                const float wv = w[ol * 9 + j];
                a = fmaf(xwA[o + j], wv, a);
                b = fmaf(xwB[o + j], wv, b);
            }
            accA[o] = a;
            accB[o] = b;
        }
    }
}

__device__ __forceinline__
void store6(float* __restrict__ dst, const float* __restrict__ acc,
            const float* __restrict__ bias6)
{
    float r0 = fmaxf(acc[0] + bias6[0], 0.0f);
    float r1 = fmaxf(acc[1] + bias6[1], 0.0f);
    float r2 = fmaxf(acc[2] + bias6[2], 0.0f);
    float r3 = fmaxf(acc[3] + bias6[3], 0.0f);
    float r4 = fmaxf(acc[4] + bias6[4], 0.0f);
    float r5 = fmaxf(acc[5] + bias6[5], 0.0f);
    reinterpret_cast<float2*>(dst)[0] = make_float2(r0, r1);
    reinterpret_cast<float2*>(dst)[1] = make_float2(r2, r3);
    reinterpret_cast<float2*>(dst)[2] = make_float2(r4, r5);
}

template<int WHI>
__device__ __forceinline__
void lc2d_compute(const float* __restrict__ XS, const float* __restrict__ WS,
                  const float* __restrict__ bias, float* __restrict__ out,
                  int hp, int lane, int h0, int w0)
{
    // acc[h-row 0/1][batch A/B][6]
    float accA0[WH], accB0[WH], accA1[WH], accB1[WH];
#pragma unroll
    for (int o = 0; o < WH; o++) {
        accA0[o] = 0.0f; accB0[o] = 0.0f;
        accA1[o] = 0.0f; accB1[o] = 0.0f;
    }

    const int hla = 2 * hp;        // local h row 0
    const int hlb = 2 * hp + 1;    // local h row 1

#pragma unroll
    for (int k = 0; k < 10; k++) {
        const int r = hla + k;     // x row for this step
        const float* xbase = XS + r * RSTRIDE + (WHI ? 6 : 0);
        float xwA[14], xwB[14];
        load_window<WHI>(xbase + lane * CP,        xwA);   // batch n = lane
        load_window<WHI>(xbase + (lane + 32) * CP, xwB);   // batch n = lane+32

        if (k <= 8) {   // h row a, tap i = k
            const float* wrow = WS + (((hla * 9 + k) * 2 + WHI) * 2) * 28;
            accum_row(wrow, xwA, xwB, accA0, accB0);
        }
        if (k >= 1) {   // h row b, tap i = k-1
            const float* wrow = WS + (((hlb * 9 + (k - 1)) * 2 + WHI) * 2) * 28;
            accum_row(wrow, xwA, xwB, accA1, accB1);
        }
    }

    // ---- epilogue: bias + relu + 4x (3x STG.64) ----
    const int cbase = WHI * WH;
    const int ha = h0 + hla;
    const int hb = h0 + hlb;
    const float* bpa = bias + (size_t)ha * 504 + w0 + cbase;
    const float* bpb = bias + (size_t)hb * 504 + w0 + cbase;
    float ba6[WH], bb6[WH];
#pragma unroll
    for (int o = 0; o < WH; o++) { ba6[o] = __ldg(bpa + o); bb6[o] = __ldg(bpb + o); }

    float* dA0 = out + ((size_t)lane        * 504 + ha) * 504 + w0 + cbase;
    float* dB0 = out + ((size_t)(lane + 32) * 504 + ha) * 504 + w0 + cbase;
    float* dA1 = out + ((size_t)lane        * 504 + hb) * 504 + w0 + cbase;
    float* dB1 = out + ((size_t)(lane + 32) * 504 + hb) * 504 + w0 + cbase;
    store6(dA0, accA0, ba6);
    store6(dB0, accB0, ba6);
    store6(dA1, accA1, bb6);
    store6(dB1, accB1, bb6);
}

__global__ __launch_bounds__(256, 2)
void lc2d_kernel(const float* __restrict__ x,
                 const float* __restrict__ wgt,
                 const float* __restrict__ bias,
                 float* __restrict__ out)
{
    extern __shared__ float sm[];
    float* XS = sm + XS_OFF;
    float* WS = sm + WS_OFF;

    const int tid  = threadIdx.x;
    const int lane = tid & 31;
    const int warp = tid >> 5;

    const int w0 = blockIdx.x * TW;   // 0..492
    const int h0 = blockIdx.y * TH;   // 0..496

    // ---- stage x: x[n, h0+r, w0+4c4..+3] -> XS[r*RSTRIDE + n*CP + 4c4] ----
    // 64 n * 16 r * 5 f4 = 5120 f4 over 256 threads: 4 threads/n, 20 f4 each
    // (exact cover, no predicate).
    {
        const int nn = tid >> 2;       // 0..63
        const int s  = tid & 3;        // 0..3
        const float* src = x + (size_t)nn * (512 * 512) + (size_t)h0 * 512 + w0;
        float* dstn = XS + nn * CP;
#pragma unroll
        for (int k = 0; k < 20; k++) {
            int m  = s + 4 * k;        // 0..79 exact
            int r  = m / 5;
            int c4 = m - r * 5;
            float4 v = *reinterpret_cast<const float4*>(src + r * 512 + c4 * 4);
            *reinterpret_cast<float4*>(dstn + r * RSTRIDE + c4 * 4) = v;
        }
    }

    // ---- stage weights: W[h0+hl, w0+o, i, j] -> WS[hl][i][wh][half][wi*9+j]
    {
        for (int t = tid; t < PIX * 81; t += 256) {   // 96*81 = 7776
            int pix = t / 81;          // hl*12 + o
            int q   = t - pix * 81;
            int i   = q / 9;
            int j   = q - i * 9;
            int hl  = pix / TW;
            int o   = pix - hl * TW;   // 0..11
            int wh  = o / 6;
            int ol  = o - wh * 6;      // 0..5
            int hf  = ol / 3;
            int wi  = ol - hf * 3;     // 0..2
            WS[(((hl * 9 + i) * 2 + wh) * 2 + hf) * 28 + wi * 9 + j] =
                wgt[((size_t)(h0 + hl) * 504 + (w0 + o)) * 81 + q];
        }
    }

    __syncthreads();

    // ---- compute: warp = (hp, wh); lane does batches lane & lane+32,
    //      h rows 2*hp and 2*hp+1 ----
    const int hp = warp >> 1;          // 0..3
    const int wh = warp & 1;           // 0..1

    if (wh == 0) lc2d_compute<0>(XS, WS, bias, out, hp, lane, h0, w0);
    else         lc2d_compute<1>(XS, WS, bias, out, hp, lane, h0, w0);
}

extern "C" void kernel_launch(void* const* d_in, const int* in_sizes, int n_in,
                              void* d_out, int out_size)
{
    const float* x    = (const float*)d_in[0];
    const float* wgt  = (const float*)d_in[1];
    const float* bias = (const float*)d_in[2];
    float* out        = (float*)d_out;

    cudaFuncSetAttribute(lc2d_kernel,
                         cudaFuncAttributeMaxDynamicSharedMemorySize,
                         SMEM_BYTES);

    dim3 grid(504 / TW, 504 / TH);   // 42 x 63 = 2646 CTAs
    lc2d_kernel<<<grid, 256, SMEM_BYTES>>>(x, wgt, bias, out);
}

// round 12
// speedup vs baseline: 1.0987x; 1.0099x over previous
#include <cuda_runtime.h>

// Locally connected 2D:
//   y[n,h,w] = relu( sum_{i,j} x[n,h+i,w+j] * W[h,w,i,j] + b[h,w] )
// N=64, H_IN=W_IN=512, K=9, H_OUT=W_OUT=504.
//
// CTA: 448 threads = 14 warps = 7 h-rows x 2 w-halves; smem 105.3KB ->
// 2 CTAs/SM = 28 warps (occ 43.75%). Each lane owns TWO batches
// (n = lane, lane+32) with independent scalar accumulators, so each
// warp-uniform weight broadcast feeds 108 FFMAs (proven crossbar diet).
// Round-series evidence: warp count dominates register-ILP for latency
// hiding here; this keeps R10's lean per-warp stream at 1.17x the warps.
// Tile: 7h x 12w x 64n (exact: 504 = 42*12 = 72*7).
// x staged [r][n][c] pitch 20 (window = 3xLDS.128 + LDS.64 per batch);
// weights packed [hl][i][wh][half][28] -> 7x broadcast LDS.128 per half.

#define TW 12            // w outputs per CTA
#define WH 6             // w outputs per thread
#define TH 7             // h rows per CTA
#define XR (TH + 8)      // 15 x rows staged
#define CP 20            // x cols staged per n (col pitch, floats)
#define RSTRIDE (64 * CP + 4)   // 1284 floats
#define PIX (TH * TW)    // 84 pixels per CTA
#define NTHREADS 448

// smem (floats): XS[XR][RSTRIDE] = 19260 ; WS[7][9][2][2][28] = 7056
#define XS_OFF 0
#define WS_OFF (XR * RSTRIDE)                      // 19260
#define SMEM_FLOATS (WS_OFF + TH * 9 * 2 * 2 * 28) // 26316
#define SMEM_BYTES (SMEM_FLOATS * 4)               // 105264

template<int WHI>   // w-half index: 0 or 1
__device__ __forceinline__
void load_window(const float* __restrict__ xrow, float* __restrict__ xw)
{
    if (WHI == 0) {
        float4 a = *reinterpret_cast<const float4*>(xrow + 0);
        float4 b = *reinterpret_cast<const float4*>(xrow + 4);
        float4 c = *reinterpret_cast<const float4*>(xrow + 8);
        float2 d = *reinterpret_cast<const float2*>(xrow + 12);
        xw[0]=a.x; xw[1]=a.y; xw[2]=a.z; xw[3]=a.w;
        xw[4]=b.x; xw[5]=b.y; xw[6]=b.z; xw[7]=b.w;
        xw[8]=c.x; xw[9]=c.y; xw[10]=c.z; xw[11]=c.w;
        xw[12]=d.x; xw[13]=d.y;
    } else {
        // window starts at col 6 (not 16B-aligned): f2 then 3x f4
        float2 d = *reinterpret_cast<const float2*>(xrow + 0);
        float4 a = *reinterpret_cast<const float4*>(xrow + 2);
        float4 b = *reinterpret_cast<const float4*>(xrow + 6);
        float4 c = *reinterpret_cast<const float4*>(xrow + 10);
        xw[0]=d.x; xw[1]=d.y;
        xw[2]=a.x; xw[3]=a.y; xw[4]=a.z; xw[5]=a.w;
        xw[6]=b.x; xw[7]=b.y; xw[8]=b.z; xw[9]=b.w;
        xw[10]=c.x; xw[11]=c.y; xw[12]=c.z; xw[13]=c.w;
    }
}

template<int WHI>
__device__ __forceinline__
void lc2d_compute(const float* __restrict__ XS, const float* __restrict__ WS,
                  const float* __restrict__ bp,
                  float* __restrict__ dstA, float* __restrict__ dstB,
                  int hl, int lane)
{
    float accA[WH], accB[WH];
#pragma unroll
    for (int o = 0; o < WH; o++) { accA[o] = 0.0f; accB[o] = 0.0f; }

#pragma unroll
    for (int i = 0; i < 9; i++) {
        const int r = hl + i;
        const float* xbase = XS + r * RSTRIDE + (WHI ? 6 : 0);
        float xwA[14], xwB[14];
        load_window<WHI>(xbase + lane * CP,        xwA);   // batch n = lane
        load_window<WHI>(xbase + (lane + 32) * CP, xwB);   // batch n = lane+32

        const float* wrow = WS + (((hl * 9 + i) * 2 + WHI) * 2) * 28;

#pragma unroll
        for (int half = 0; half < 2; half++) {
            const float* wb = wrow + half * 28;
            float w[28];
#pragma unroll
            for (int k = 0; k < 7; k++) {
                float4 v = *reinterpret_cast<const float4*>(wb + 4 * k);  // broadcast
                w[4*k+0]=v.x; w[4*k+1]=v.y; w[4*k+2]=v.z; w[4*k+3]=v.w;
            }
#pragma unroll
            for (int ol = 0; ol < 3; ol++) {
                const int o = half * 3 + ol;
                float a = accA[o];
                float b = accB[o];
#pragma unroll
                for (int j = 0; j < 9; j++) {
                    const float wv = w[ol * 9 + j];
                    a = fmaf(xwA[o + j], wv, a);
                    b = fmaf(xwB[o + j], wv, b);
                }
                accA[o] = a;
                accB[o] = b;
            }
        }
    }

    // bias + relu + direct stores (3x STG.64 per batch)
    float bias6[WH];
#pragma unroll
    for (int o = 0; o < WH; o++) bias6[o] = __ldg(bp + o);

    float a0 = fmaxf(accA[0] + bias6[0], 0.0f);
    float a1 = fmaxf(accA[1] + bias6[1], 0.0f);
    float a2 = fmaxf(accA[2] + bias6[2], 0.0f);
    float a3 = fmaxf(accA[3] + bias6[3], 0.0f);
    float a4 = fmaxf(accA[4] + bias6[4], 0.0f);
    float a5 = fmaxf(accA[5] + bias6[5], 0.0f);
    reinterpret_cast<float2*>(dstA)[0] = make_float2(a0, a1);
    reinterpret_cast<float2*>(dstA)[1] = make_float2(a2, a3);
    reinterpret_cast<float2*>(dstA)[2] = make_float2(a4, a5);

    float b0 = fmaxf(accB[0] + bias6[0], 0.0f);
    float b1 = fmaxf(accB[1] + bias6[1], 0.0f);
    float b2 = fmaxf(accB[2] + bias6[2], 0.0f);
    float b3 = fmaxf(accB[3] + bias6[3], 0.0f);
    float b4 = fmaxf(accB[4] + bias6[4], 0.0f);
    float b5 = fmaxf(accB[5] + bias6[5], 0.0f);
    reinterpret_cast<float2*>(dstB)[0] = make_float2(b0, b1);
    reinterpret_cast<float2*>(dstB)[1] = make_float2(b2, b3);
    reinterpret_cast<float2*>(dstB)[2] = make_float2(b4, b5);
}

__global__ __launch_bounds__(NTHREADS, 2)
void lc2d_kernel(const float* __restrict__ x,
                 const float* __restrict__ wgt,
                 const float* __restrict__ bias,
                 float* __restrict__ out)
{
    extern __shared__ float sm[];
    float* XS = sm + XS_OFF;
    float* WS = sm + WS_OFF;

    const int tid  = threadIdx.x;
    const int lane = tid & 31;
    const int warp = tid >> 5;

    const int w0 = blockIdx.x * TW;   // 0..492
    const int h0 = blockIdx.y * TH;   // 0..497

    // ---- stage x: x[n, h0+r, w0+4c4..+3] -> XS[r*RSTRIDE + n*CP + 4c4] ----
    // 64 n * 15 r * 5 f4 = 4800 f4 over 448 threads: 7 threads per n,
    // each covers m = s + 7k (m < 75).
    {
        const int nn = tid / 7;        // 0..63
        const int s  = tid - nn * 7;   // 0..6
        const float* src = x + (size_t)nn * (512 * 512) + (size_t)h0 * 512 + w0;
        float* dstn = XS + nn * CP;
#pragma unroll
        for (int k = 0; k < 11; k++) {
            int m = s + 7 * k;         // 0..76
            if (m < 75) {
                int r  = m / 5;
                int c4 = m - r * 5;
                float4 v = *reinterpret_cast<const float4*>(src + r * 512 + c4 * 4);
                *reinterpret_cast<float4*>(dstn + r * RSTRIDE + c4 * 4) = v;
            }
        }
    }

    // ---- stage weights: W[h0+hl, w0+o, i, j] -> WS[hl][i][wh][half][wi*9+j]
    {
        for (int t = tid; t < PIX * 81; t += NTHREADS) {   // 84*81 = 6804
            int pix = t / 81;          // hl*12 + o
            int q   = t - pix * 81;
            int i   = q / 9;
            int j   = q - i * 9;
            int hl  = pix / TW;
            int o   = pix - hl * TW;   // 0..11
            int wh  = o / 6;
            int ol  = o - wh * 6;      // 0..5
            int hf  = ol / 3;
            int wi  = ol - hf * 3;     // 0..2
            WS[(((hl * 9 + i) * 2 + wh) * 2 + hf) * 28 + wi * 9 + j] =
                wgt[((size_t)(h0 + hl) * 504 + (w0 + o)) * 81 + q];
        }
    }

    __syncthreads();

    // ---- compute: warp = (hl, wh); each lane does batches lane & lane+32 ----
    const int hl = warp >> 1;          // 0..6
    const int wh = warp & 1;           // 0..1
    const int h  = h0 + hl;
    const int cbase = wh * WH;         // 0 or 6

    const float* bp   = bias + (size_t)h * 504 + w0 + cbase;
    float* dstA = out + ((size_t)lane        * 504 + h) * 504 + w0 + cbase;
    float* dstB = out + ((size_t)(lane + 32) * 504 + h) * 504 + w0 + cbase;

    if (wh == 0) lc2d_compute<0>(XS, WS, bp, dstA, dstB, hl, lane);
    else         lc2d_compute<1>(XS, WS, bp, dstA, dstB, hl, lane);
}

extern "C" void kernel_launch(void* const* d_in, const int* in_sizes, int n_in,
                              void* d_out, int out_size)
{
    const float* x    = (const float*)d_in[0];
    const float* wgt  = (const float*)d_in[1];
    const float* bias = (const float*)d_in[2];
    float* out        = (float*)d_out;

    cudaFuncSetAttribute(lc2d_kernel,
                         cudaFuncAttributeMaxDynamicSharedMemorySize,
                         SMEM_BYTES);

    dim3 grid(504 / TW, 504 / TH);   // 42 x 72 = 3024 CTAs
    lc2d_kernel<<<grid, NTHREADS, SMEM_BYTES>>>(x, wgt, bias, out);
}

// round 13
// speedup vs baseline: 1.6942x; 1.5419x over previous
#include <cuda_runtime.h>
#include <cstdint>

// Locally connected 2D:
//   y[n,h,w] = relu( sum_{i,j} x[n,h+i,w+j] * W[h,w,i,j] + b[h,w] )
// N=64, H_IN=W_IN=512, K=9, H_OUT=W_OUT=504.
//
// CTA: 448 threads = 14 warps = 7 h-rows x 2 w-halves; 2 CTAs/SM = 28 warps.
// Each lane owns TWO batches (n = lane, lane+32): warp-uniform weight
// broadcasts feed 108 FFMAs each (proven crossbar diet). This round: the
// staging phase is rewritten with cp.async + warp-per-pixel weight layout
// (lane-constant index math) -- R12 measured alu work ~1.2x fma work, mostly
// from per-element div chains + LDG->STS round trips in staging.
// Compute loop is IDENTICAL to R12.

#define TW 12            // w outputs per CTA
#define WH 6             // w outputs per thread
#define TH 7             // h rows per CTA
#define XR (TH + 8)      // 15 x rows staged
#define CP 20            // x cols staged per n (col pitch, floats)
#define RSTRIDE (64 * CP + 4)   // 1284 floats
#define PIX (TH * TW)    // 84 pixels per CTA
#define NTHREADS 448

// smem (floats): XS[XR][RSTRIDE] = 19260 ; WS[7][9][2][2][28] = 7056
// WS flat index: hl*1008 + i*112 + wh*56 + hf*28 + wi*9 + j
#define XS_OFF 0
#define WS_OFF (XR * RSTRIDE)                      // 19260
#define SMEM_FLOATS (WS_OFF + TH * 9 * 2 * 2 * 28) // 26316
#define SMEM_BYTES (SMEM_FLOATS * 4)               // 105264

__device__ __forceinline__ void cp16(uint32_t dst, const void* src) {
    asm volatile("cp.async.cg.shared.global [%0], [%1], 16;" :: "r"(dst), "l"(src));
}
__device__ __forceinline__ void cp4(uint32_t dst, const void* src) {
    asm volatile("cp.async.ca.shared.global [%0], [%1], 4;" :: "r"(dst), "l"(src));
}
__device__ __forceinline__ void cp_commit_wait() {
    asm volatile("cp.async.commit_group;" ::: "memory");
    asm volatile("cp.async.wait_group 0;" ::: "memory");
}

template<int WHI>   // w-half index: 0 or 1
__device__ __forceinline__
void load_window(const float* __restrict__ xrow, float* __restrict__ xw)
{
    if (WHI == 0) {
        float4 a = *reinterpret_cast<const float4*>(xrow + 0);
        float4 b = *reinterpret_cast<const float4*>(xrow + 4);
        float4 c = *reinterpret_cast<const float4*>(xrow + 8);
        float2 d = *reinterpret_cast<const float2*>(xrow + 12);
        xw[0]=a.x; xw[1]=a.y; xw[2]=a.z; xw[3]=a.w;
        xw[4]=b.x; xw[5]=b.y; xw[6]=b.z; xw[7]=b.w;
        xw[8]=c.x; xw[9]=c.y; xw[10]=c.z; xw[11]=c.w;
        xw[12]=d.x; xw[13]=d.y;
    } else {
        float2 d = *reinterpret_cast<const float2*>(xrow + 0);
        float4 a = *reinterpret_cast<const float4*>(xrow + 2);
        float4 b = *reinterpret_cast<const float4*>(xrow + 6);
        float4 c = *reinterpret_cast<const float4*>(xrow + 10);
        xw[0]=d.x; xw[1]=d.y;
        xw[2]=a.x; xw[3]=a.y; xw[4]=a.z; xw[5]=a.w;
        xw[6]=b.x; xw[7]=b.y; xw[8]=b.z; xw[9]=b.w;
        xw[10]=c.x; xw[11]=c.y; xw[12]=c.z; xw[13]=c.w;
    }
}

template<int WHI>
__device__ __forceinline__
void lc2d_compute(const float* __restrict__ XS, const float* __restrict__ WS,
                  const float* __restrict__ bp,
                  float* __restrict__ dstA, float* __restrict__ dstB,
                  int hl, int lane)
{
    float accA[WH], accB[WH];
#pragma unroll
    for (int o = 0; o < WH; o++) { accA[o] = 0.0f; accB[o] = 0.0f; }

#pragma unroll
    for (int i = 0; i < 9; i++) {
        const int r = hl + i;
        const float* xbase = XS + r * RSTRIDE + (WHI ? 6 : 0);
        float xwA[14], xwB[14];
        load_window<WHI>(xbase + lane * CP,        xwA);   // batch n = lane
        load_window<WHI>(xbase + (lane + 32) * CP, xwB);   // batch n = lane+32

        // WS flat: hl*1008 + i*112 + WHI*56 + hf*28 + ...
        const float* wrow = WS + hl * 1008 + i * 112 + WHI * 56;

#pragma unroll
        for (int half = 0; half < 2; half++) {
            const float* wb = wrow + half * 28;
            float w[28];
#pragma unroll
            for (int k = 0; k < 7; k++) {
                float4 v = *reinterpret_cast<const float4*>(wb + 4 * k);  // broadcast
                w[4*k+0]=v.x; w[4*k+1]=v.y; w[4*k+2]=v.z; w[4*k+3]=v.w;
            }
#pragma unroll
            for (int ol = 0; ol < 3; ol++) {
                const int o = half * 3 + ol;
                float a = accA[o];
                float b = accB[o];
#pragma unroll
                for (int j = 0; j < 9; j++) {
                    const float wv = w[ol * 9 + j];
                    a = fmaf(xwA[o + j], wv, a);
                    b = fmaf(xwB[o + j], wv, b);
                }
                accA[o] = a;
                accB[o] = b;
            }
        }
    }

    // bias + relu + direct stores (3x STG.64 per batch); bias via 3x LDG.64
    float bias6[WH];
    {
        float2 b01 = __ldg(reinterpret_cast<const float2*>(bp + 0));
        float2 b23 = __ldg(reinterpret_cast<const float2*>(bp + 2));
        float2 b45 = __ldg(reinterpret_cast<const float2*>(bp + 4));
        bias6[0]=b01.x; bias6[1]=b01.y; bias6[2]=b23.x;
        bias6[3]=b23.y; bias6[4]=b45.x; bias6[5]=b45.y;
    }

    float a0 = fmaxf(accA[0] + bias6[0], 0.0f);
    float a1 = fmaxf(accA[1] + bias6[1], 0.0f);
    float a2 = fmaxf(accA[2] + bias6[2], 0.0f);
    float a3 = fmaxf(accA[3] + bias6[3], 0.0f);
    float a4 = fmaxf(accA[4] + bias6[4], 0.0f);
    float a5 = fmaxf(accA[5] + bias6[5], 0.0f);
    reinterpret_cast<float2*>(dstA)[0] = make_float2(a0, a1);
    reinterpret_cast<float2*>(dstA)[1] = make_float2(a2, a3);
    reinterpret_cast<float2*>(dstA)[2] = make_float2(a4, a5);

    float b0 = fmaxf(accB[0] + bias6[0], 0.0f);
    float b1 = fmaxf(accB[1] + bias6[1], 0.0f);
    float b2 = fmaxf(accB[2] + bias6[2], 0.0f);
    float b3 = fmaxf(accB[3] + bias6[3], 0.0f);
    float b4 = fmaxf(accB[4] + bias6[4], 0.0f);
    float b5 = fmaxf(accB[5] + bias6[5], 0.0f);
    reinterpret_cast<float2*>(dstB)[0] = make_float2(b0, b1);
    reinterpret_cast<float2*>(dstB)[1] = make_float2(b2, b3);
    reinterpret_cast<float2*>(dstB)[2] = make_float2(b4, b5);
}

__global__ __launch_bounds__(NTHREADS, 2)
void lc2d_kernel(const float* __restrict__ x,
                 const float* __restrict__ wgt,
                 const float* __restrict__ bias,
                 float* __restrict__ out)
{
    extern __shared__ float sm[];
    float* XS = sm + XS_OFF;
    float* WS = sm + WS_OFF;

    const int tid  = threadIdx.x;
    const int lane = tid & 31;
    const int warp = tid >> 5;

    const int w0 = blockIdx.x * TW;   // 0..492
    const int h0 = blockIdx.y * TH;   // 0..497

    // ---- stage x via cp.async.cg 16B: 64 n * 15 r * 5 f4, 7 threads/n ----
    {
        const int nn = tid / 7;        // 0..63
        const int s  = tid - nn * 7;   // 0..6
        const float* src = x + (size_t)nn * (512 * 512) + (size_t)h0 * 512 + w0;
        uint32_t dstn = (uint32_t)__cvta_generic_to_shared(XS + nn * CP);
#pragma unroll
        for (int k = 0; k < 11; k++) {
            int m = s + 7 * k;         // 0..76
            if (m < 75) {
                int r  = m / 5;
                int c4 = m - r * 5;
                cp16(dstn + (uint32_t)(r * RSTRIDE + c4 * 4) * 4u,
                     src + r * 512 + c4 * 4);
            }
        }
    }

    // ---- stage weights, warp-per-pixel: warp stages pixels warp + 14*pp ----
    // lane covers taps j = lane, lane+32, lane+64 (last predicated).
    // dest: WS + hl*1008 + i*112 + wh*56 + hf*28 + wi*9 + jj  (i = j/9, jj = j%9)
    {
        const int j0 = lane,      i0 = j0 / 9, r0 = j0 - 9 * i0;
        const int j1 = lane + 32, i1 = j1 / 9, r1 = j1 - 9 * i1;
        const int j2 = lane + 64, i2 = j2 / 9, r2 = j2 - 9 * i2;
        const uint32_t wsbase = (uint32_t)__cvta_generic_to_shared(WS);
#pragma unroll
        for (int pp = 0; pp < 6; pp++) {
            int pix = warp + pp * 14;      // 0..83
            int hl  = pix / TW;
            int o   = pix - hl * TW;       // 0..11
            int wh  = o / 6;
            int ol  = o - wh * 6;
            int hf  = ol / 3;
            int wi  = ol - hf * 3;
            const float* gsrc = wgt + ((size_t)(h0 + hl) * 504 + (w0 + o)) * 81;
            uint32_t d = wsbase + (uint32_t)(hl * 1008 + wh * 56 + hf * 28 + wi * 9) * 4u;
            cp4(d + (uint32_t)(i0 * 112 + r0) * 4u, gsrc + j0);
            cp4(d + (uint32_t)(i1 * 112 + r1) * 4u, gsrc + j1);
            if (lane < 17)
                cp4(d + (uint32_t)(i2 * 112 + r2) * 4u, gsrc + j2);
        }
    }

    cp_commit_wait();
    __syncthreads();

    // ---- compute: warp = (hl, wh); each lane does batches lane & lane+32 ----
    const int hl = warp >> 1;          // 0..6
    const int wh = warp & 1;           // 0..1
    const int h  = h0 + hl;
    const int cbase = wh * WH;         // 0 or 6

    const float* bp   = bias + (size_t)h * 504 + w0 + cbase;
    float* dstA = out + ((size_t)lane        * 504 + h) * 504 + w0 + cbase;
    float* dstB = out + ((size_t)(lane + 32) * 504 + h) * 504 + w0 + cbase;

    if (wh == 0) lc2d_compute<0>(XS, WS, bp, dstA, dstB, hl, lane);
    else         lc2d_compute<1>(XS, WS, bp, dstA, dstB, hl, lane);
}

extern "C" void kernel_launch(void* const* d_in, const int* in_sizes, int n_in,
                              void* d_out, int out_size)
{
    const float* x    = (const float*)d_in[0];
    const float* wgt  = (const float*)d_in[1];
    const float* bias = (const float*)d_in[2];
    float* out        = (float*)d_out;

    cudaFuncSetAttribute(lc2d_kernel,
                         cudaFuncAttributeMaxDynamicSharedMemorySize,
                         SMEM_BYTES);

    dim3 grid(504 / TW, 504 / TH);   // 42 x 72 = 3024 CTAs
    lc2d_kernel<<<grid, NTHREADS, SMEM_BYTES>>>(x, wgt, bias, out);
}

// round 14
// speedup vs baseline: 1.7204x; 1.0155x over previous
#include <cuda_runtime.h>
#include <cstdint>

// Locally connected 2D:
//   y[n,h,w] = relu( sum_{i,j} x[n,h+i,w+j] * W[h,w,i,j] + b[h,w] )
// N=64, H_IN=W_IN=512, K=9, H_OUT=W_OUT=504.
//
// R11 compute (h-pair register blocking) + R13 staging (cp.async):
// CTA: 256 threads = 8 warps = 4 h-pairs x 2 w-halves; 2 CTAs/SM = 16 warps.
// Each thread: 2 adjacent h rows x 6 w x 2 batches (n = lane, lane+32) = 24
// outputs. The two h rows share 8/10 x rows -> each x window LDS feeds both
// rows: smem bytes/FFMA drop 33% vs R13 (0.39 -> 0.26 wf/FFMA), and per-
// thread ILP is 24 independent FFMA chains. Staging is all cp.async
// (16B for x, 4B warp-per-pixel for weights) -- proven worth 90us in R13.
// Tile: 8h x 12w x 64n (504 = 63*8 = 42*12).

#define TW 12            // w outputs per CTA
#define WH 6             // w outputs per thread
#define TH 8             // h rows per CTA (4 pairs)
#define XR (TH + 8)      // 16 x rows staged
#define CP 20            // x cols staged per n (col pitch, floats)
#define RSTRIDE (64 * CP + 4)   // 1284 floats
#define PIX (TH * TW)    // 96 pixels per CTA
#define NTHREADS 256

// smem (floats): XS[XR][RSTRIDE] = 20544 ; WS[8][9][2][2][28] = 8064
// WS flat index: hl*1008 + i*112 + wh*56 + hf*28 + wi*9 + j
#define XS_OFF 0
#define WS_OFF (XR * RSTRIDE)                      // 20544
#define SMEM_FLOATS (WS_OFF + TH * 9 * 2 * 2 * 28) // 28608
#define SMEM_BYTES (SMEM_FLOATS * 4)               // 114432

__device__ __forceinline__ void cp16(uint32_t dst, const void* src) {
    asm volatile("cp.async.cg.shared.global [%0], [%1], 16;" :: "r"(dst), "l"(src));
}
__device__ __forceinline__ void cp4(uint32_t dst, const void* src) {
    asm volatile("cp.async.ca.shared.global [%0], [%1], 4;" :: "r"(dst), "l"(src));
}
__device__ __forceinline__ void cp_commit_wait() {
    asm volatile("cp.async.commit_group;" ::: "memory");
    asm volatile("cp.async.wait_group 0;" ::: "memory");
}

template<int WHI>   // w-half index: 0 or 1
__device__ __forceinline__
void load_window(const float* __restrict__ xrow, float* __restrict__ xw)
{
    if (WHI == 0) {
        float4 a = *reinterpret_cast<const float4*>(xrow + 0);
        float4 b = *reinterpret_cast<const float4*>(xrow + 4);
        float4 c = *reinterpret_cast<const float4*>(xrow + 8);
        float2 d = *reinterpret_cast<const float2*>(xrow + 12);
        xw[0]=a.x; xw[1]=a.y; xw[2]=a.z; xw[3]=a.w;
        xw[4]=b.x; xw[5]=b.y; xw[6]=b.z; xw[7]=b.w;
        xw[8]=c.x; xw[9]=c.y; xw[10]=c.z; xw[11]=c.w;
        xw[12]=d.x; xw[13]=d.y;
    } else {
        float2 d = *reinterpret_cast<const float2*>(xrow + 0);
        float4 a = *reinterpret_cast<const float4*>(xrow + 2);
        float4 b = *reinterpret_cast<const float4*>(xrow + 6);
        float4 c = *reinterpret_cast<const float4*>(xrow + 10);
        xw[0]=d.x; xw[1]=d.y;
        xw[2]=a.x; xw[3]=a.y; xw[4]=a.z; xw[5]=a.w;
        xw[6]=b.x; xw[7]=b.y; xw[8]=b.z; xw[9]=b.w;
        xw[10]=c.x; xw[11]=c.y; xw[12]=c.z; xw[13]=c.w;
    }
}

// Accumulate one tap row for one output h-row (both batches).
__device__ __forceinline__
void accum_row(const float* __restrict__ wrow,
               const float* __restrict__ xwA, const float* __restrict__ xwB,
               float* __restrict__ accA, float* __restrict__ accB)
{
#pragma unroll
    for (int half = 0; half < 2; half++) {
        const float* wb = wrow + half * 28;
        float w[28];
#pragma unroll
        for (int k = 0; k < 7; k++) {
            float4 v = *reinterpret_cast<const float4*>(wb + 4 * k);  // broadcast
            w[4*k+0]=v.x; w[4*k+1]=v.y; w[4*k+2]=v.z; w[4*k+3]=v.w;
        }
#pragma unroll
        for (int ol = 0; ol < 3; ol++) {
            const int o = half * 3 + ol;
            float a = accA[o];
            float b = accB[o];
#pragma unroll
            for (int j = 0; j < 9; j++) {
                const float wv = w[ol * 9 + j];
                a = fmaf(xwA[o + j], wv, a);
                b = fmaf(xwB[o + j], wv, b);
            }
            accA[o] = a;
            accB[o] = b;
        }
    }
}

__device__ __forceinline__
void store6(float* __restrict__ dst, const float* __restrict__ acc,
            const float* __restrict__ bias6)
{
    float r0 = fmaxf(acc[0] + bias6[0], 0.0f);
    float r1 = fmaxf(acc[1] + bias6[1], 0.0f);
    float r2 = fmaxf(acc[2] + bias6[2], 0.0f);
    float r3 = fmaxf(acc[3] + bias6[3], 0.0f);
    float r4 = fmaxf(acc[4] + bias6[4], 0.0f);
    float r5 = fmaxf(acc[5] + bias6[5], 0.0f);
    reinterpret_cast<float2*>(dst)[0] = make_float2(r0, r1);
    reinterpret_cast<float2*>(dst)[1] = make_float2(r2, r3);
    reinterpret_cast<float2*>(dst)[2] = make_float2(r4, r5);
}

template<int WHI>
__device__ __forceinline__
void lc2d_compute(const float* __restrict__ XS, const float* __restrict__ WS,
                  const float* __restrict__ bias, float* __restrict__ out,
                  int hp, int lane, int h0, int w0)
{
    float accA0[WH], accB0[WH], accA1[WH], accB1[WH];
#pragma unroll
    for (int o = 0; o < WH; o++) {
        accA0[o] = 0.0f; accB0[o] = 0.0f;
        accA1[o] = 0.0f; accB1[o] = 0.0f;
    }

    const int hla = 2 * hp;        // local h row 0
    const int hlb = 2 * hp + 1;    // local h row 1

#pragma unroll
    for (int k = 0; k < 10; k++) {
        const int r = hla + k;     // x row for this step
        const float* xbase = XS + r * RSTRIDE + (WHI ? 6 : 0);
        float xwA[14], xwB[14];
        load_window<WHI>(xbase + lane * CP,        xwA);   // batch n = lane
        load_window<WHI>(xbase + (lane + 32) * CP, xwB);   // batch n = lane+32

        if (k <= 8) {   // h row a, tap i = k
            const float* wrow = WS + hla * 1008 + k * 112 + WHI * 56;
            accum_row(wrow, xwA, xwB, accA0, accB0);
        }
        if (k >= 1) {   // h row b, tap i = k-1
            const float* wrow = WS + hlb * 1008 + (k - 1) * 112 + WHI * 56;
            accum_row(wrow, xwA, xwB, accA1, accB1);
        }
    }

    // ---- epilogue: bias (LDG.64 x3 per row) + relu + 4x (3x STG.64) ----
    const int cbase = WHI * WH;
    const int ha = h0 + hla;
    const int hb = h0 + hlb;
    const float* bpa = bias + (size_t)ha * 504 + w0 + cbase;
    const float* bpb = bias + (size_t)hb * 504 + w0 + cbase;
    float ba6[WH], bb6[WH];
    {
        float2 v0 = __ldg(reinterpret_cast<const float2*>(bpa + 0));
        float2 v1 = __ldg(reinterpret_cast<const float2*>(bpa + 2));
        float2 v2 = __ldg(reinterpret_cast<const float2*>(bpa + 4));
        ba6[0]=v0.x; ba6[1]=v0.y; ba6[2]=v1.x; ba6[3]=v1.y; ba6[4]=v2.x; ba6[5]=v2.y;
        float2 u0 = __ldg(reinterpret_cast<const float2*>(bpb + 0));
        float2 u1 = __ldg(reinterpret_cast<const float2*>(bpb + 2));
        float2 u2 = __ldg(reinterpret_cast<const float2*>(bpb + 4));
        bb6[0]=u0.x; bb6[1]=u0.y; bb6[2]=u1.x; bb6[3]=u1.y; bb6[4]=u2.x; bb6[5]=u2.y;
    }

    float* dA0 = out + ((size_t)lane        * 504 + ha) * 504 + w0 + cbase;
    float* dB0 = out + ((size_t)(lane + 32) * 504 + ha) * 504 + w0 + cbase;
    float* dA1 = out + ((size_t)lane        * 504 + hb) * 504 + w0 + cbase;
    float* dB1 = out + ((size_t)(lane + 32) * 504 + hb) * 504 + w0 + cbase;
    store6(dA0, accA0, ba6);
    store6(dB0, accB0, ba6);
    store6(dA1, accA1, bb6);
    store6(dB1, accB1, bb6);
}

__global__ __launch_bounds__(NTHREADS, 2)
void lc2d_kernel(const float* __restrict__ x,
                 const float* __restrict__ wgt,
                 const float* __restrict__ bias,
                 float* __restrict__ out)
{
    extern __shared__ float sm[];
    float* XS = sm + XS_OFF;
    float* WS = sm + WS_OFF;

    const int tid  = threadIdx.x;
    const int lane = tid & 31;
    const int warp = tid >> 5;

    const int w0 = blockIdx.x * TW;   // 0..492
    const int h0 = blockIdx.y * TH;   // 0..496

    // ---- stage x via cp.async.cg 16B ----
    // 64 n * 16 r * 5 f4 = 5120 f4 over 256 threads: 4 threads/n, 20 f4 each
    // (exact cover, no predicate).
    {
        const int nn = tid >> 2;       // 0..63
        const int s  = tid & 3;        // 0..3
        const float* src = x + (size_t)nn * (512 * 512) + (size_t)h0 * 512 + w0;
        uint32_t dstn = (uint32_t)__cvta_generic_to_shared(XS + nn * CP);
#pragma unroll
        for (int k = 0; k < 20; k++) {
            int m  = s + 4 * k;        // 0..79 exact
            int r  = m / 5;
            int c4 = m - r * 5;
            cp16(dstn + (uint32_t)(r * RSTRIDE + c4 * 4) * 4u,
                 src + r * 512 + c4 * 4);
        }
    }

    // ---- stage weights, warp-per-pixel: warp stages pixels warp + 8*pp ----
    // lane covers taps j = lane, lane+32, lane+64 (last predicated, lane<17).
    // dest: WS + hl*1008 + i*112 + wh*56 + hf*28 + wi*9 + jj  (i=j/9, jj=j%9)
    {
        const int j0 = lane,      i0 = j0 / 9, r0 = j0 - 9 * i0;
        const int j1 = lane + 32, i1 = j1 / 9, r1 = j1 - 9 * i1;
        const int j2 = lane + 64, i2 = j2 / 9, r2 = j2 - 9 * i2;
        const uint32_t wsbase = (uint32_t)__cvta_generic_to_shared(WS);
#pragma unroll
        for (int pp = 0; pp < 12; pp++) {
            int pix = warp + pp * 8;       // 0..95
            int hl  = pix / TW;
            int o   = pix - hl * TW;       // 0..11
            int wh  = o / 6;
            int ol  = o - wh * 6;
            int hf  = ol / 3;
            int wi  = ol - hf * 3;
            const float* gsrc = wgt + ((size_t)(h0 + hl) * 504 + (w0 + o)) * 81;
            uint32_t d = wsbase + (uint32_t)(hl * 1008 + wh * 56 + hf * 28 + wi * 9) * 4u;
            cp4(d + (uint32_t)(i0 * 112 + r0) * 4u, gsrc + j0);
            cp4(d + (uint32_t)(i1 * 112 + r1) * 4u, gsrc + j1);
            if (lane < 17)
                cp4(d + (uint32_t)(i2 * 112 + r2) * 4u, gsrc + j2);
        }
    }

    cp_commit_wait();
    __syncthreads();

    // ---- compute: warp = (hp, wh); lane does batches lane & lane+32,
    //      h rows 2*hp and 2*hp+1 ----
    const int hp = warp >> 1;          // 0..3
    const int wh = warp & 1;           // 0..1

    if (wh == 0) lc2d_compute<0>(XS, WS, bias, out, hp, lane, h0, w0);
    else         lc2d_compute<1>(XS, WS, bias, out, hp, lane, h0, w0);
}

extern "C" void kernel_launch(void* const* d_in, const int* in_sizes, int n_in,
                              void* d_out, int out_size)
{
    const float* x    = (const float*)d_in[0];
    const float* wgt  = (const float*)d_in[1];
    const float* bias = (const float*)d_in[2];
    float* out        = (float*)d_out;

    cudaFuncSetAttribute(lc2d_kernel,
                         cudaFuncAttributeMaxDynamicSharedMemorySize,
                         SMEM_BYTES);

    dim3 grid(504 / TW, 504 / TH);   // 42 x 63 = 2646 CTAs
    lc2d_kernel<<<grid, NTHREADS, SMEM_BYTES>>>(x, wgt, bias, out);
}

// round 15
// speedup vs baseline: 2.0420x; 1.1870x over previous
#include <cuda_runtime.h>
#include <cstdint>

// Locally connected 2D:
//   y[n,h,w] = relu( sum_{i,j} x[n,h+i,w+j] * W[h,w,i,j] + b[h,w] )
// N=64, H_IN=W_IN=512, K=9, H_OUT=W_OUT=504.
//
// CTA: 384 threads = 12 warps = 4 h-pairs x 3 w-thirds; 2 CTAs/SM = 24 warps.
// Thread: 2 adjacent h x 4 w x 2 batches (n = lane, lane+32) = 16 outputs.
// - h-pair: the two h rows share 8/10 x rows -> each x window feeds both
//   rows (proven crossbar diet, R14).
// - 3-way w split: window offsets 0/4/8 are all 16B-aligned -> window is
//   exactly 3x LDS.128; weight row (4 outputs x 9 taps = 36 floats) is
//   exactly 9x LDS.128 broadcast. Epilogue: STG.128 stores, LDG.128 bias.
// - 24 warps/SM at 0.29 wf/FFMA: combines R13's warp count with (nearly)
//   R14's crossbar ratio.
// Staging: all cp.async (16B x, 4B warp-per-pixel weights) -- R13's win.
// Tile: 8h x 12w x 64n (504 = 63*8 = 42*12).

#define TW 12            // w outputs per CTA
#define WH 4             // w outputs per thread (third)
#define TH 8             // h rows per CTA (4 pairs)
#define XR (TH + 8)      // 16 x rows staged
#define CP 20            // x cols staged per n (col pitch, floats)
#define RSTRIDE (64 * CP + 4)   // 1284 floats
#define PIX (TH * TW)    // 96 pixels per CTA
#define NTHREADS 384

// smem (floats): XS[XR][RSTRIDE] = 20544 ; WS[8][9][3][36] = 7776
// WS flat index: hl*972 + i*108 + wt*36 + wi*9 + j
#define XS_OFF 0
#define WS_OFF (XR * RSTRIDE)                  // 20544
#define SMEM_FLOATS (WS_OFF + TH * 9 * 3 * 36) // 28320
#define SMEM_BYTES (SMEM_FLOATS * 4)           // 113280

__device__ __forceinline__ void cp16(uint32_t dst, const void* src) {
    asm volatile("cp.async.cg.shared.global [%0], [%1], 16;" :: "r"(dst), "l"(src));
}
__device__ __forceinline__ void cp4(uint32_t dst, const void* src) {
    asm volatile("cp.async.ca.shared.global [%0], [%1], 4;" :: "r"(dst), "l"(src));
}
__device__ __forceinline__ void cp_commit_wait() {
    asm volatile("cp.async.commit_group;" ::: "memory");
    asm volatile("cp.async.wait_group 0;" ::: "memory");
}

// Load 12-col window (3x aligned LDS.128).
__device__ __forceinline__
void load_window12(const float* __restrict__ xrow, float* __restrict__ xw)
{
    float4 a = reinterpret_cast<const float4*>(xrow)[0];
    float4 b = reinterpret_cast<const float4*>(xrow)[1];
    float4 c = reinterpret_cast<const float4*>(xrow)[2];
    xw[0]=a.x; xw[1]=a.y; xw[2]=a.z;  xw[3]=a.w;
    xw[4]=b.x; xw[5]=b.y; xw[6]=b.z;  xw[7]=b.w;
    xw[8]=c.x; xw[9]=c.y; xw[10]=c.z; xw[11]=c.w;
}

// One tap row (9 taps) for 4 outputs x 2 batches: 9x broadcast LDS.128 + 72 FFMA.
__device__ __forceinline__
void accum_row4(const float* __restrict__ wrow,
                const float* __restrict__ xwA, const float* __restrict__ xwB,
                float* __restrict__ accA, float* __restrict__ accB)
{
    float w[36];
#pragma unroll
    for (int k = 0; k < 9; k++) {
        float4 v = reinterpret_cast<const float4*>(wrow)[k];  // broadcast
        w[4*k+0]=v.x; w[4*k+1]=v.y; w[4*k+2]=v.z; w[4*k+3]=v.w;
    }
#pragma unroll
    for (int o = 0; o < WH; o++) {
        float a = accA[o];
        float b = accB[o];
#pragma unroll
        for (int j = 0; j < 9; j++) {
            const float wv = w[o * 9 + j];
            a = fmaf(xwA[o + j], wv, a);
            b = fmaf(xwB[o + j], wv, b);
        }
        accA[o] = a;
        accB[o] = b;
    }
}

__device__ __forceinline__
void store4(float* __restrict__ dst, const float* __restrict__ acc,
            const float4 b4)
{
    float4 v;
    v.x = fmaxf(acc[0] + b4.x, 0.0f);
    v.y = fmaxf(acc[1] + b4.y, 0.0f);
    v.z = fmaxf(acc[2] + b4.z, 0.0f);
    v.w = fmaxf(acc[3] + b4.w, 0.0f);
    *reinterpret_cast<float4*>(dst) = v;   // STG.128 (16B-aligned)
}

template<int WT>   // w-third index: 0, 1, 2
__device__ __forceinline__
void lc2d_compute(const float* __restrict__ XS, const float* __restrict__ WS,
                  const float* __restrict__ bias, float* __restrict__ out,
                  int hp, int lane, int h0, int w0)
{
    float accA0[WH], accB0[WH], accA1[WH], accB1[WH];
#pragma unroll
    for (int o = 0; o < WH; o++) {
        accA0[o] = 0.0f; accB0[o] = 0.0f;
        accA1[o] = 0.0f; accB1[o] = 0.0f;
    }

    const int hla = 2 * hp;        // local h row 0
    const int hlb = 2 * hp + 1;    // local h row 1
    const int CO  = 4 * WT;        // window col offset (16B-aligned)

#pragma unroll
    for (int k = 0; k < 10; k++) {
        const int r = hla + k;     // x row for this step
        const float* xbase = XS + r * RSTRIDE + CO;
        float xwA[12], xwB[12];
        load_window12(xbase + lane * CP,        xwA);   // batch n = lane
        load_window12(xbase + (lane + 32) * CP, xwB);   // batch n = lane+32

        if (k <= 8) {   // h row a, tap i = k
            accum_row4(WS + hla * 972 + k * 108 + WT * 36, xwA, xwB, accA0, accB0);
        }
        if (k >= 1) {   // h row b, tap i = k-1
            accum_row4(WS + hlb * 972 + (k - 1) * 108 + WT * 36, xwA, xwB, accA1, accB1);
        }
    }

    // ---- epilogue: bias (LDG.128) + relu + 4x STG.128 ----
    const int ha = h0 + hla;
    const int hb = h0 + hlb;
    const float4 ba = __ldg(reinterpret_cast<const float4*>(
                            bias + (size_t)ha * 504 + w0 + CO));
    const float4 bb = __ldg(reinterpret_cast<const float4*>(
                            bias + (size_t)hb * 504 + w0 + CO));

    float* dA0 = out + ((size_t)lane        * 504 + ha) * 504 + w0 + CO;
    float* dB0 = out + ((size_t)(lane + 32) * 504 + ha) * 504 + w0 + CO;
    float* dA1 = out + ((size_t)lane        * 504 + hb) * 504 + w0 + CO;
    float* dB1 = out + ((size_t)(lane + 32) * 504 + hb) * 504 + w0 + CO;
    store4(dA0, accA0, ba);
    store4(dB0, accB0, ba);
    store4(dA1, accA1, bb);
    store4(dB1, accB1, bb);
}

__global__ __launch_bounds__(NTHREADS, 2)
void lc2d_kernel(const float* __restrict__ x,
                 const float* __restrict__ wgt,
                 const float* __restrict__ bias,
                 float* __restrict__ out)
{
    extern __shared__ float sm[];
    float* XS = sm + XS_OFF;
    float* WS = sm + WS_OFF;

    const int tid  = threadIdx.x;
    const int lane = tid & 31;
    const int warp = tid >> 5;

    const int w0 = blockIdx.x * TW;   // 0..492
    const int h0 = blockIdx.y * TH;   // 0..496

    // ---- stage x via cp.async.cg 16B ----
    // 64 n * 16 r * 5 f4 = 5120 f4 over 384 threads: 6 threads/n,
    // each covers m = s + 6k (m < 80).
    {
        const int nn = tid / 6;        // 0..63
        const int s  = tid - nn * 6;   // 0..5
        const float* src = x + (size_t)nn * (512 * 512) + (size_t)h0 * 512 + w0;
        uint32_t dstn = (uint32_t)__cvta_generic_to_shared(XS + nn * CP);
#pragma unroll
        for (int k = 0; k < 14; k++) {
            int m = s + 6 * k;         // 0..83
            if (m < 80) {
                int r  = m / 5;
                int c4 = m - r * 5;
                cp16(dstn + (uint32_t)(r * RSTRIDE + c4 * 4) * 4u,
                     src + r * 512 + c4 * 4);
            }
        }
    }

    // ---- stage weights, warp-per-pixel: warp stages pixels warp + 12*pp ----
    // lane covers taps j = lane, lane+32, lane+64 (last predicated, lane<17).
    // dest: WS + hl*972 + i*108 + wt*36 + wi*9 + jj   (i = j/9, jj = j%9)
    {
        const int j0 = lane,      i0 = j0 / 9, r0 = j0 - 9 * i0;
        const int j1 = lane + 32, i1 = j1 / 9, r1 = j1 - 9 * i1;
        const int j2 = lane + 64, i2 = j2 / 9, r2 = j2 - 9 * i2;
        const uint32_t wsbase = (uint32_t)__cvta_generic_to_shared(WS);
#pragma unroll
        for (int pp = 0; pp < 8; pp++) {
            int pix = warp + pp * 12;      // 0..95
            int hl  = pix / TW;
            int o   = pix - hl * TW;       // 0..11
            int wt  = o / 4;               // 0..2
            int wi  = o - wt * 4;          // 0..3
            const float* gsrc = wgt + ((size_t)(h0 + hl) * 504 + (w0 + o)) * 81;
            uint32_t d = wsbase + (uint32_t)(hl * 972 + wt * 36 + wi * 9) * 4u;
            cp4(d + (uint32_t)(i0 * 108 + r0) * 4u, gsrc + j0);
            cp4(d + (uint32_t)(i1 * 108 + r1) * 4u, gsrc + j1);
            if (lane < 17)
                cp4(d + (uint32_t)(i2 * 108 + r2) * 4u, gsrc + j2);
        }
    }

    cp_commit_wait();
    __syncthreads();

    // ---- compute: warp = (hp, wt); lane does batches lane & lane+32,
    //      h rows 2*hp and 2*hp+1, w outputs [w0+4*wt .. +3] ----
    const int hp = warp >> 2;          // 0..3  (warp = hp*... see below)
    // NOTE: use warp % 3 / warp / 3 mapping instead: 12 warps = 4 hp x 3 wt
    const int hp2 = warp / 3;          // 0..3
    const int wt  = warp - hp2 * 3;    // 0..2
    (void)hp;

    if      (wt == 0) lc2d_compute<0>(XS, WS, bias, out, hp2, lane, h0, w0);
    else if (wt == 1) lc2d_compute<1>(XS, WS, bias, out, hp2, lane, h0, w0);
    else              lc2d_compute<2>(XS, WS, bias, out, hp2, lane, h0, w0);
}

extern "C" void kernel_launch(void* const* d_in, const int* in_sizes, int n_in,
                              void* d_out, int out_size)
{
    const float* x    = (const float*)d_in[0];
    const float* wgt  = (const float*)d_in[1];
    const float* bias = (const float*)d_in[2];
    float* out        = (float*)d_out;

    cudaFuncSetAttribute(lc2d_kernel,
                         cudaFuncAttributeMaxDynamicSharedMemorySize,
                         SMEM_BYTES);

    dim3 grid(504 / TW, 504 / TH);   // 42 x 63 = 2646 CTAs
    lc2d_kernel<<<grid, NTHREADS, SMEM_BYTES>>>(x, wgt, bias, out);
}

// round 16
// speedup vs baseline: 2.0694x; 1.0134x over previous
#include <cuda_runtime.h>
#include <cstdint>

// Locally connected 2D:
//   y[n,h,w] = relu( sum_{i,j} x[n,h+i,w+j] * W[h,w,i,j] + b[h,w] )
// N=64, H_IN=W_IN=512, K=9, H_OUT=W_OUT=504.
//
// CTA: 384 threads = 12 warps = 4 h-pairs x 3 w-thirds; 2 CTAs/SM = 24 warps.
// Thread: 2 adjacent h x 4 w x 2 batches (n = lane, lane+32) = 16 outputs.
// R16 change vs R15: weights are STREAMED through 4 live registers (load one
// float4 -> consume its 8 FFMAs immediately, compile-time (o,j) split of
// m = 4k+t) instead of materializing w[36]. Live architectural regs drop
// ~80 -> ~60, giving ptxas ~25 spare registers under the same 85-reg cap to
// software-pipeline next-k window LDS over the FFMA stream (R15 had only 5
// spare; issue stalled at 42.8% with no pipe saturated).
// Everything else (layout, staging, tiling) identical to R15.

#define TW 12            // w outputs per CTA
#define WH 4             // w outputs per thread (third)
#define TH 8             // h rows per CTA (4 pairs)
#define XR (TH + 8)      // 16 x rows staged
#define CP 20            // x cols staged per n (col pitch, floats)
#define RSTRIDE (64 * CP + 4)   // 1284 floats
#define PIX (TH * TW)    // 96 pixels per CTA
#define NTHREADS 384

// smem (floats): XS[XR][RSTRIDE] = 20544 ; WS[8][9][3][36] = 7776
// WS flat index: hl*972 + i*108 + wt*36 + wi*9 + j
#define XS_OFF 0
#define WS_OFF (XR * RSTRIDE)                  // 20544
#define SMEM_FLOATS (WS_OFF + TH * 9 * 3 * 36) // 28320
#define SMEM_BYTES (SMEM_FLOATS * 4)           // 113280

__device__ __forceinline__ void cp16(uint32_t dst, const void* src) {
    asm volatile("cp.async.cg.shared.global [%0], [%1], 16;" :: "r"(dst), "l"(src));
}
__device__ __forceinline__ void cp4(uint32_t dst, const void* src) {
    asm volatile("cp.async.ca.shared.global [%0], [%1], 4;" :: "r"(dst), "l"(src));
}
__device__ __forceinline__ void cp_commit_wait() {
    asm volatile("cp.async.commit_group;" ::: "memory");
    asm volatile("cp.async.wait_group 0;" ::: "memory");
}

// Load 12-col window (3x aligned LDS.128).
__device__ __forceinline__
void load_window12(const float* __restrict__ xrow, float* __restrict__ xw)
{
    float4 a = reinterpret_cast<const float4*>(xrow)[0];
    float4 b = reinterpret_cast<const float4*>(xrow)[1];
    float4 c = reinterpret_cast<const float4*>(xrow)[2];
    xw[0]=a.x; xw[1]=a.y; xw[2]=a.z;  xw[3]=a.w;
    xw[4]=b.x; xw[5]=b.y; xw[6]=b.z;  xw[7]=b.w;
    xw[8]=c.x; xw[9]=c.y; xw[10]=c.z; xw[11]=c.w;
}

// One tap row (9 taps) for 4 outputs x 2 batches, weight-STREAMING form:
// 9x (broadcast LDS.128 -> 8 dependent FFMAs). Live weight regs = 4.
__device__ __forceinline__
void accum_row4(const float* __restrict__ wrow,
                const float* __restrict__ xwA, const float* __restrict__ xwB,
                float* __restrict__ accA, float* __restrict__ accB)
{
#pragma unroll
    for (int k4 = 0; k4 < 9; k4++) {
        const float4 v = reinterpret_cast<const float4*>(wrow)[k4];  // broadcast
        const float wv[4] = { v.x, v.y, v.z, v.w };
#pragma unroll
        for (int t = 0; t < 4; t++) {
            const int m = 4 * k4 + t;   // 0..35, compile-time
            const int o = m / 9;
            const int j = m - 9 * o;
            accA[o] = fmaf(xwA[o + j], wv[t], accA[o]);
            accB[o] = fmaf(xwB[o + j], wv[t], accB[o]);
        }
    }
}

__device__ __forceinline__
void store4(float* __restrict__ dst, const float* __restrict__ acc,
            const float4 b4)
{
    float4 v;
    v.x = fmaxf(acc[0] + b4.x, 0.0f);
    v.y = fmaxf(acc[1] + b4.y, 0.0f);
    v.z = fmaxf(acc[2] + b4.z, 0.0f);
    v.w = fmaxf(acc[3] + b4.w, 0.0f);
    *reinterpret_cast<float4*>(dst) = v;   // STG.128 (16B-aligned)
}

template<int WT>   // w-third index: 0, 1, 2
__device__ __forceinline__
void lc2d_compute(const float* __restrict__ XS, const float* __restrict__ WS,
                  const float* __restrict__ bias, float* __restrict__ out,
                  int hp, int lane, int h0, int w0)
{
    float accA0[WH], accB0[WH], accA1[WH], accB1[WH];
#pragma unroll
    for (int o = 0; o < WH; o++) {
        accA0[o] = 0.0f; accB0[o] = 0.0f;
        accA1[o] = 0.0f; accB1[o] = 0.0f;
    }

    const int hla = 2 * hp;        // local h row 0
    const int hlb = 2 * hp + 1;    // local h row 1
    const int CO  = 4 * WT;        // window col offset (16B-aligned)

#pragma unroll
    for (int k = 0; k < 10; k++) {
        const int r = hla + k;     // x row for this step
        const float* xbase = XS + r * RSTRIDE + CO;
        float xwA[12], xwB[12];
        load_window12(xbase + lane * CP,        xwA);   // batch n = lane
        load_window12(xbase + (lane + 32) * CP, xwB);   // batch n = lane+32

        if (k <= 8) {   // h row a, tap i = k
            accum_row4(WS + hla * 972 + k * 108 + WT * 36, xwA, xwB, accA0, accB0);
        }
        if (k >= 1) {   // h row b, tap i = k-1
            accum_row4(WS + hlb * 972 + (k - 1) * 108 + WT * 36, xwA, xwB, accA1, accB1);
        }
    }

    // ---- epilogue: bias (LDG.128) + relu + 4x STG.128 ----
    const int ha = h0 + hla;
    const int hb = h0 + hlb;
    const float4 ba = __ldg(reinterpret_cast<const float4*>(
                            bias + (size_t)ha * 504 + w0 + CO));
    const float4 bb = __ldg(reinterpret_cast<const float4*>(
                            bias + (size_t)hb * 504 + w0 + CO));

    float* dA0 = out + ((size_t)lane        * 504 + ha) * 504 + w0 + CO;
    float* dB0 = out + ((size_t)(lane + 32) * 504 + ha) * 504 + w0 + CO;
    float* dA1 = out + ((size_t)lane        * 504 + hb) * 504 + w0 + CO;
    float* dB1 = out + ((size_t)(lane + 32) * 504 + hb) * 504 + w0 + CO;
    store4(dA0, accA0, ba);
    store4(dB0, accB0, ba);
    store4(dA1, accA1, bb);
    store4(dB1, accB1, bb);
}

__global__ __launch_bounds__(NTHREADS, 2)
void lc2d_kernel(const float* __restrict__ x,
                 const float* __restrict__ wgt,
                 const float* __restrict__ bias,
                 float* __restrict__ out)
{
    extern __shared__ float sm[];
    float* XS = sm + XS_OFF;
    float* WS = sm + WS_OFF;

    const int tid  = threadIdx.x;
    const int lane = tid & 31;
    const int warp = tid >> 5;

    const int w0 = blockIdx.x * TW;   // 0..492
    const int h0 = blockIdx.y * TH;   // 0..496

    // ---- stage x via cp.async.cg 16B ----
    // 64 n * 16 r * 5 f4 = 5120 f4 over 384 threads: 6 threads/n,
    // each covers m = s + 6k (m < 80).
    {
        const int nn = tid / 6;        // 0..63
        const int s  = tid - nn * 6;   // 0..5
        const float* src = x + (size_t)nn * (512 * 512) + (size_t)h0 * 512 + w0;
        uint32_t dstn = (uint32_t)__cvta_generic_to_shared(XS + nn * CP);
#pragma unroll
        for (int k = 0; k < 14; k++) {
            int m = s + 6 * k;         // 0..83
            if (m < 80) {
                int r  = m / 5;
                int c4 = m - r * 5;
                cp16(dstn + (uint32_t)(r * RSTRIDE + c4 * 4) * 4u,
                     src + r * 512 + c4 * 4);
            }
        }
    }

    // ---- stage weights, warp-per-pixel: warp stages pixels warp + 12*pp ----
    // lane covers taps j = lane, lane+32, lane+64 (last predicated, lane<17).
    // dest: WS + hl*972 + i*108 + wt*36 + wi*9 + jj   (i = j/9, jj = j%9)
    {
        const int j0 = lane,      i0 = j0 / 9, r0 = j0 - 9 * i0;
        const int j1 = lane + 32, i1 = j1 / 9, r1 = j1 - 9 * i1;
        const int j2 = lane + 64, i2 = j2 / 9, r2 = j2 - 9 * i2;
        const uint32_t wsbase = (uint32_t)__cvta_generic_to_shared(WS);
#pragma unroll
        for (int pp = 0; pp < 8; pp++) {
            int pix = warp + pp * 12;      // 0..95
            int hl  = pix / TW;
            int o   = pix - hl * TW;       // 0..11
            int wt  = o / 4;               // 0..2
            int wi  = o - wt * 4;          // 0..3
            const float* gsrc = wgt + ((size_t)(h0 + hl) * 504 + (w0 + o)) * 81;
            uint32_t d = wsbase + (uint32_t)(hl * 972 + wt * 36 + wi * 9) * 4u;
            cp4(d + (uint32_t)(i0 * 108 + r0) * 4u, gsrc + j0);
            cp4(d + (uint32_t)(i1 * 108 + r1) * 4u, gsrc + j1);
            if (lane < 17)
                cp4(d + (uint32_t)(i2 * 108 + r2) * 4u, gsrc + j2);
        }
    }

    cp_commit_wait();
    __syncthreads();

    // ---- compute: 12 warps = 4 h-pairs x 3 w-thirds ----
    const int hp = warp / 3;           // 0..3
    const int wt = warp - hp * 3;      // 0..2

    if      (wt == 0) lc2d_compute<0>(XS, WS, bias, out, hp, lane, h0, w0);
    else if (wt == 1) lc2d_compute<1>(XS, WS, bias, out, hp, lane, h0, w0);
    else              lc2d_compute<2>(XS, WS, bias, out, hp, lane, h0, w0);
}

extern "C" void kernel_launch(void* const* d_in, const int* in_sizes, int n_in,
                              void* d_out, int out_size)
{
    const float* x    = (const float*)d_in[0];
    const float* wgt  = (const float*)d_in[1];
    const float* bias = (const float*)d_in[2];
    float* out        = (float*)d_out;

    cudaFuncSetAttribute(lc2d_kernel,
                         cudaFuncAttributeMaxDynamicSharedMemorySize,
                         SMEM_BYTES);

    dim3 grid(504 / TW, 504 / TH);   // 42 x 63 = 2646 CTAs
    lc2d_kernel<<<grid, NTHREADS, SMEM_BYTES>>>(x, wgt, bias, out);
}

// round 17
// speedup vs baseline: 2.1122x; 1.0207x over previous
#include <cuda_runtime.h>
#include <cstdint>

// Locally connected 2D:
//   y[n,h,w] = relu( sum_{i,j} x[n,h+i,w+j] * W[h,w,i,j] + b[h,w] )
// N=64, H_IN=W_IN=512, K=9, H_OUT=W_OUT=504.
//
// CTA: 384 threads = 12 warps = 4 h-pairs x 3 w-thirds; 2 CTAs/SM = 24 warps.
// Thread: 2 adjacent h x 4 w x 2 batches = 16 outputs.
// R17: FFMA2 (fma.rn.f32x2) paired over the TWO H-ROWS. Both rows share the
// x window, so x pairs are {x,x} dups (cheap MOV); weights are staged
// PRE-INTERLEAVED {w_rowa(tap k), w_rowb(tap k-1)} so one LDS.128 delivers
// two aligned FFMA2 weight operands with zero packing MOVs (the fix for
// R2's f32x2 failure). FMA-pipe demand (rt2, measured at ~58% of capacity)
// drops 44%: 144 FFMA -> 72 FFMA2 per k-step. Boundary steps k=0/9 use
// {w,0}/{0,w} pairs built inline; smem identical to R16 (113,280B, 2 CTAs).
// Numerics bit-identical to scalar FFMA.

#define TW 12            // w outputs per CTA
#define WH 4             // w outputs per thread (third)
#define TH 8             // h rows per CTA (4 pairs)
#define XR (TH + 8)      // 16 x rows staged
#define CP 20            // x cols staged per n (col pitch, floats)
#define RSTRIDE (64 * CP + 4)   // 1284 floats
#define PIX (TH * TW)    // 96 pixels per CTA
#define NTHREADS 384

// smem (floats):
//   XS  [XR][RSTRIDE]            = 20544
//   WSP [4 hp][8 k][3 wt][36*2]  =  6912  (interior weight PAIRS, k=1..8)
//   WSB [4 hp][3 wt][2 side][36] =   864  (boundary scalar rows: a/tap0, b/tap8)
#define XS_OFF 0
#define WSP_OFF (XR * RSTRIDE)                 // 20544
#define WSB_OFF (WSP_OFF + 4 * 8 * 3 * 72)     // 27456
#define SMEM_FLOATS (WSB_OFF + 4 * 3 * 2 * 36) // 28320
#define SMEM_BYTES (SMEM_FLOATS * 4)           // 113280

typedef unsigned long long u64;

__device__ __forceinline__ void cp16(uint32_t dst, const void* src) {
    asm volatile("cp.async.cg.shared.global [%0], [%1], 16;" :: "r"(dst), "l"(src));
}
__device__ __forceinline__ void cp4(uint32_t dst, const void* src) {
    asm volatile("cp.async.ca.shared.global [%0], [%1], 4;" :: "r"(dst), "l"(src));
}
__device__ __forceinline__ void cp_commit_wait() {
    asm volatile("cp.async.commit_group;" ::: "memory");
    asm volatile("cp.async.wait_group 0;" ::: "memory");
}

__device__ __forceinline__ u64 ffma2(u64 a, u64 b, u64 c) {
    u64 d;
    asm("fma.rn.f32x2 %0, %1, %2, %3;" : "=l"(d) : "l"(a), "l"(b), "l"(c));
    return d;
}
__device__ __forceinline__ u64 dup2(float x) {
    u64 d;
    asm("mov.b64 %0, {%1, %1};" : "=l"(d) : "f"(x));
    return d;
}
__device__ __forceinline__ u64 pack2(float lo, float hi) {
    u64 d;
    asm("mov.b64 %0, {%1, %2};" : "=l"(d) : "f"(lo), "f"(hi));
    return d;
}
__device__ __forceinline__ void unpack2(u64 v, float& lo, float& hi) {
    asm("mov.b64 {%0, %1}, %2;" : "=f"(lo), "=f"(hi) : "l"(v));
}

// Load 12-col window (3x aligned LDS.128) and duplicate each value into a
// {x,x} f32x2 pair (feeds both h-rows of the pair).
__device__ __forceinline__
void load_dup12(const float* __restrict__ xrow, u64* __restrict__ x2)
{
    float4 a = reinterpret_cast<const float4*>(xrow)[0];
    float4 b = reinterpret_cast<const float4*>(xrow)[1];
    float4 c = reinterpret_cast<const float4*>(xrow)[2];
    x2[0]=dup2(a.x); x2[1]=dup2(a.y); x2[2] =dup2(a.z); x2[3] =dup2(a.w);
    x2[4]=dup2(b.x); x2[5]=dup2(b.y); x2[6] =dup2(b.z); x2[7] =dup2(b.w);
    x2[8]=dup2(c.x); x2[9]=dup2(c.y); x2[10]=dup2(c.z); x2[11]=dup2(c.w);
}

// Interior step: 36 pre-interleaved weight pairs (18x LDS.128 broadcast),
// 72 FFMA2 total (4 outputs x 9 taps x 2 batches).
__device__ __forceinline__
void accum_pair(const u64* __restrict__ wrow2,
                const u64* __restrict__ a2, const u64* __restrict__ b2,
                u64* __restrict__ pA, u64* __restrict__ pB)
{
#pragma unroll
    for (int m = 0; m < 18; m++) {
        const ulonglong2 W = reinterpret_cast<const ulonglong2*>(wrow2)[m];
        const int q0 = 2 * m,      wi0 = q0 / 9, j0 = q0 - 9 * wi0;
        const int q1 = 2 * m + 1,  wi1 = q1 / 9, j1 = q1 - 9 * wi1;
        pA[wi0] = ffma2(a2[wi0 + j0], W.x, pA[wi0]);
        pB[wi0] = ffma2(b2[wi0 + j0], W.x, pB[wi0]);
        pA[wi1] = ffma2(a2[wi1 + j1], W.y, pA[wi1]);
        pB[wi1] = ffma2(b2[wi1 + j1], W.y, pB[wi1]);
    }
}

// Boundary step: scalar 36-weight row, partner slot zeroed.
// SIDE=0: row a active (lo slot); SIDE=1: row b active (hi slot).
template<int SIDE>
__device__ __forceinline__
void accum_boundary(const float* __restrict__ wrow,
                    const u64* __restrict__ a2, const u64* __restrict__ b2,
                    u64* __restrict__ pA, u64* __restrict__ pB)
{
#pragma unroll
    for (int m = 0; m < 9; m++) {
        const float4 v = reinterpret_cast<const float4*>(wrow)[m];
        const float wv[4] = { v.x, v.y, v.z, v.w };
#pragma unroll
        for (int t = 0; t < 4; t++) {
            const int q = 4 * m + t;
            const int wi = q / 9, j = q - 9 * wi;
            const u64 wp = (SIDE == 0) ? pack2(wv[t], 0.0f) : pack2(0.0f, wv[t]);
            pA[wi] = ffma2(a2[wi + j], wp, pA[wi]);
            pB[wi] = ffma2(b2[wi + j], wp, pB[wi]);
        }
    }
}

__device__ __forceinline__
void store4(float* __restrict__ dst, const float* __restrict__ acc,
            const float4 b4)
{
    float4 v;
    v.x = fmaxf(acc[0] + b4.x, 0.0f);
    v.y = fmaxf(acc[1] + b4.y, 0.0f);
    v.z = fmaxf(acc[2] + b4.z, 0.0f);
    v.w = fmaxf(acc[3] + b4.w, 0.0f);
    *reinterpret_cast<float4*>(dst) = v;   // STG.128
}

template<int WT>   // w-third index: 0, 1, 2
__device__ __forceinline__
void lc2d_compute(const float* __restrict__ XS, const float* __restrict__ sm,
                  const float* __restrict__ bias, float* __restrict__ out,
                  int hp, int lane, int h0, int w0)
{
    u64 pA[WH], pB[WH];   // {row_a, row_b} accumulators, batches A/B
#pragma unroll
    for (int o = 0; o < WH; o++) { pA[o] = 0ull; pB[o] = 0ull; }

    const int hla = 2 * hp;
    const int CO  = 4 * WT;

    // k = 0: row a, tap 0 only
    {
        const float* xbase = XS + hla * RSTRIDE + CO;
        u64 a2[12], b2[12];
        load_dup12(xbase + lane * CP,        a2);
        load_dup12(xbase + (lane + 32) * CP, b2);
        accum_boundary<0>(sm + WSB_OFF + ((hp * 3 + WT) * 2 + 0) * 36,
                          a2, b2, pA, pB);
    }

    // k = 1..8: interior pairs (row a tap k, row b tap k-1)
#pragma unroll
    for (int k = 1; k <= 8; k++) {
        const float* xbase = XS + (hla + k) * RSTRIDE + CO;
        u64 a2[12], b2[12];
        load_dup12(xbase + lane * CP,        a2);
        load_dup12(xbase + (lane + 32) * CP, b2);
        const u64* wrow2 = reinterpret_cast<const u64*>(
            sm + WSP_OFF + (((hp * 8) + (k - 1)) * 3 + WT) * 72);
        accum_pair(wrow2, a2, b2, pA, pB);
    }

    // k = 9: row b, tap 8 only
    {
        const float* xbase = XS + (hla + 9) * RSTRIDE + CO;
        u64 a2[12], b2[12];
        load_dup12(xbase + lane * CP,        a2);
        load_dup12(xbase + (lane + 32) * CP, b2);
        accum_boundary<1>(sm + WSB_OFF + ((hp * 3 + WT) * 2 + 1) * 36,
                          a2, b2, pA, pB);
    }

    // ---- epilogue: unpack pairs, bias (LDG.128) + relu + 4x STG.128 ----
    float A0[WH], A1[WH], B0[WH], B1[WH];
#pragma unroll
    for (int o = 0; o < WH; o++) {
        unpack2(pA[o], A0[o], A1[o]);   // batch A: row a, row b
        unpack2(pB[o], B0[o], B1[o]);   // batch B: row a, row b
    }

    const int ha = h0 + hla;
    const int hb = h0 + hla + 1;
    const float4 ba = __ldg(reinterpret_cast<const float4*>(
                            bias + (size_t)ha * 504 + w0 + CO));
    const float4 bb = __ldg(reinterpret_cast<const float4*>(
                            bias + (size_t)hb * 504 + w0 + CO));

    float* dA0 = out + ((size_t)lane        * 504 + ha) * 504 + w0 + CO;
    float* dB0 = out + ((size_t)(lane + 32) * 504 + ha) * 504 + w0 + CO;
    float* dA1 = out + ((size_t)lane        * 504 + hb) * 504 + w0 + CO;
    float* dB1 = out + ((size_t)(lane + 32) * 504 + hb) * 504 + w0 + CO;
    store4(dA0, A0, ba);
    store4(dB0, B0, ba);
    store4(dA1, A1, bb);
    store4(dB1, B1, bb);
}

__global__ __launch_bounds__(NTHREADS, 2)
void lc2d_kernel(const float* __restrict__ x,
                 const float* __restrict__ wgt,
                 const float* __restrict__ bias,
                 float* __restrict__ out)
{
    extern __shared__ float sm[];
    float* XS = sm + XS_OFF;

    const int tid  = threadIdx.x;
    const int lane = tid & 31;
    const int warp = tid >> 5;

    const int w0 = blockIdx.x * TW;   // 0..492
    const int h0 = blockIdx.y * TH;   // 0..496

    // ---- stage x via cp.async.cg 16B (unchanged from R16) ----
    {
        const int nn = tid / 6;        // 0..63
        const int s  = tid - nn * 6;   // 0..5
        const float* src = x + (size_t)nn * (512 * 512) + (size_t)h0 * 512 + w0;
        uint32_t dstn = (uint32_t)__cvta_generic_to_shared(XS + nn * CP);
#pragma unroll
        for (int k = 0; k < 14; k++) {
            int m = s + 6 * k;         // 0..83
            if (m < 80) {
                int r  = m / 5;
                int c4 = m - r * 5;
                cp16(dstn + (uint32_t)(r * RSTRIDE + c4 * 4) * 4u,
                     src + r * 512 + c4 * 4);
            }
        }
    }

    // ---- stage weights (cp.async 4B, warp-per-pixel) into PAIRED layout ----
    // Pixel (hl, o): hp = hl>>1, rb = hl&1, wt = o/4, wi = o%4. Tap (i,j):
    //   rb=0, i==0 -> WSB side 0;  rb=0, i>0  -> WSP[k=i]   slot 0
    //   rb=1, i==8 -> WSB side 1;  rb=1, i<8  -> WSP[k=i+1] slot 1
    {
        const int j0 = lane,      i0 = j0 / 9, r0 = j0 - 9 * i0;
        const int j1 = lane + 32, i1 = j1 / 9, r1 = j1 - 9 * i1;
        const int j2 = lane + 64, i2 = j2 / 9, r2 = j2 - 9 * i2;
        const uint32_t smbase = (uint32_t)__cvta_generic_to_shared(sm);
#pragma unroll
        for (int pp = 0; pp < 8; pp++) {
            int pix = warp + pp * 12;      // 0..95
            int hl  = pix / TW;
            int o   = pix - hl * TW;       // 0..11
            int hp  = hl >> 1;
            int rb  = hl & 1;
            int wt  = o / 4;               // 0..2
            int wi  = o - wt * 4;          // 0..3
            const float* gsrc = wgt + ((size_t)(h0 + hl) * 504 + (w0 + o)) * 81;

            // per-slot destination (float index into sm[])
            uint32_t d0, d1, d2;
            if (rb == 0) {
                d0 = (i0 == 0) ? (uint32_t)(WSB_OFF + ((hp*3+wt)*2+0)*36 + wi*9 + r0)
                               : (uint32_t)(WSP_OFF + (((hp*8)+(i0-1))*3+wt)*72 + (wi*9+r0)*2 + 0);
                d1 = (i1 == 0) ? (uint32_t)(WSB_OFF + ((hp*3+wt)*2+0)*36 + wi*9 + r1)
                               : (uint32_t)(WSP_OFF + (((hp*8)+(i1-1))*3+wt)*72 + (wi*9+r1)*2 + 0);
                d2 = (i2 == 0) ? (uint32_t)(WSB_OFF + ((hp*3+wt)*2+0)*36 + wi*9 + r2)
                               : (uint32_t)(WSP_OFF + (((hp*8)+(i2-1))*3+wt)*72 + (wi*9+r2)*2 + 0);
            } else {
                d0 = (i0 == 8) ? (uint32_t)(WSB_OFF + ((hp*3+wt)*2+1)*36 + wi*9 + r0)
                               : (uint32_t)(WSP_OFF + (((hp*8)+i0)*3+wt)*72 + (wi*9+r0)*2 + 1);
                d1 = (i1 == 8) ? (uint32_t)(WSB_OFF + ((hp*3+wt)*2+1)*36 + wi*9 + r1)
                               : (uint32_t)(WSP_OFF + (((hp*8)+i1)*3+wt)*72 + (wi*9+r1)*2 + 1);
                d2 = (i2 == 8) ? (uint32_t)(WSB_OFF + ((hp*3+wt)*2+1)*36 + wi*9 + r2)
                               : (uint32_t)(WSP_OFF + (((hp*8)+i2)*3+wt)*72 + (wi*9+r2)*2 + 1);
            }
            cp4(smbase + d0 * 4u, gsrc + j0);
            cp4(smbase + d1 * 4u, gsrc + j1);
            if (lane < 17)
                cp4(smbase + d2 * 4u, gsrc + j2);
        }
    }

    cp_commit_wait();
    __syncthreads();

    // ---- compute: 12 warps = 4 h-pairs x 3 w-thirds ----
    const int hp = warp / 3;           // 0..3
    const int wt = warp - hp * 3;      // 0..2

    if      (wt == 0) lc2d_compute<0>(XS, sm, bias, out, hp, lane, h0, w0);
    else if (wt == 1) lc2d_compute<1>(XS, sm, bias, out, hp, lane, h0, w0);
    else              lc2d_compute<2>(XS, sm, bias, out, hp, lane, h0, w0);
}

extern "C" void kernel_launch(void* const* d_in, const int* in_sizes, int n_in,
                              void* d_out, int out_size)
{
    const float* x    = (const float*)d_in[0];
    const float* wgt  = (const float*)d_in[1];
    const float* bias = (const float*)d_in[2];
    float* out        = (float*)d_out;

    cudaFuncSetAttribute(lc2d_kernel,
                         cudaFuncAttributeMaxDynamicSharedMemorySize,
                         SMEM_BYTES);

    dim3 grid(504 / TW, 504 / TH);   // 42 x 63 = 2646 CTAs
    lc2d_kernel<<<grid, NTHREADS, SMEM_BYTES>>>(x, wgt, bias, out);
}